// round 4
// baseline (speedup 1.0000x reference)
#include <cuda_runtime.h>
#include <math.h>
#include <stdint.h>

#define CK_B   4
#define CK_S   512
#define CK_D   2048
#define CK_H   16
#define CK_KV  4
#define CK_HD  128
#define CK_T   2048          // B*S
#define CK_FFN 5632
#define CK_E   8
#define CK_R   16
#define CK_LS  2.0f          // 32/16

// ---------------------------------------------------------------------------
// Scratch (static device arrays — allocation-free, graph-safe)
// ---------------------------------------------------------------------------
__device__ float g_h   [CK_T*CK_D];
__device__ float g_hn  [CK_T*CK_D];
__device__ float g_xq  [CK_T*CK_D];
__device__ float g_xk  [CK_T*CK_KV*CK_HD];
__device__ float g_xv  [CK_T*CK_KV*CK_HD];
__device__ float g_sc  [(size_t)CK_B*CK_H*CK_S*CK_S];
__device__ float g_ao  [CK_T*CK_D];
__device__ float g_d2  [CK_T*CK_D];
__device__ float g_uq  [CK_T*CK_R];
__device__ float g_uk  [CK_T*CK_R];
__device__ float g_uv  [CK_T*CK_R];
__device__ float g_uo  [CK_T*CK_R];
__device__ float g_route[CK_T*CK_E];
__device__ float g_ua1 [CK_T*CK_E*CK_R];
__device__ float g_ua3 [CK_T*CK_E*CK_R];
__device__ float g_h1  [(size_t)CK_T*CK_FFN];
__device__ float g_h3  [(size_t)CK_T*CK_FFN];
__device__ float g_ghs [(size_t)CK_T*CK_FFN];
__device__ float g_v2  [CK_T*CK_E*CK_R];
__device__ float g_fpre[CK_T*CK_D];

// ---------------------------------------------------------------------------
// RMSNorm: one block per token
// ---------------------------------------------------------------------------
__global__ void k_rmsnorm(const float* __restrict__ x, const float* __restrict__ w,
                          float* __restrict__ o) {
    int t = blockIdx.x;
    const float* xr = x + (size_t)t*CK_D;
    float ss = 0.f;
    for (int i = threadIdx.x; i < CK_D; i += 256) { float v = xr[i]; ss += v*v; }
    __shared__ float red[256];
    red[threadIdx.x] = ss; __syncthreads();
    for (int s = 128; s > 0; s >>= 1) {
        if (threadIdx.x < s) red[threadIdx.x] += red[threadIdx.x+s];
        __syncthreads();
    }
    float sc = rsqrtf(red[0]/(float)CK_D + 1e-5f);
    float* orow = o + (size_t)t*CK_D;
    for (int i = threadIdx.x; i < CK_D; i += 256) orow[i] = xr[i]*sc*w[i];
}

// ---------------------------------------------------------------------------
// LoRA down-projection: U[t,r] = sum_d X[t,d]*A[r,d], R=16, block per token
// ---------------------------------------------------------------------------
__global__ void k_lora_down(const float* __restrict__ X, const float* __restrict__ A,
                            float* __restrict__ U) {
    int t = blockIdx.x;
    __shared__ float sx[CK_D];
    for (int i = threadIdx.x; i < CK_D; i += 256) sx[i] = X[(size_t)t*CK_D + i];
    __syncthreads();
    int w = threadIdx.x >> 5, lane = threadIdx.x & 31;
    for (int r = w; r < CK_R; r += 8) {
        const float* ar = A + (size_t)r*CK_D;
        float p = 0.f;
        for (int d = lane; d < CK_D; d += 32) p += sx[d]*ar[d];
        for (int o = 16; o; o >>= 1) p += __shfl_down_sync(0xffffffffu, p, o);
        if (lane == 0) U[t*CK_R + r] = p;
    }
}

// ---------------------------------------------------------------------------
// SGEMM: C = A(MxK) @ W(NxK)^T  [+ lscale * U(Mx16) @ V(Nx16)^T] [+ res]
// 128x128x16 tiles, 256 threads, 8x8 micro-tile
// ---------------------------------------------------------------------------
__global__ void __launch_bounds__(256) k_sgemm(
    const float* __restrict__ A, const float* __restrict__ W, float* __restrict__ C,
    int M, int N, int K,
    const float* __restrict__ U, const float* __restrict__ V, float lscale,
    const float* __restrict__ res)
{
    __shared__ float As[16][128];
    __shared__ float Bs[16][128];
    const int bm = blockIdx.y*128, bn = blockIdx.x*128;
    const int tid = threadIdx.x;
    const int ty = tid >> 4, tx = tid & 15;
    const int lrow = tid >> 2;
    const int lk = (tid & 3)*4;
    float acc[8][8];
    #pragma unroll
    for (int i = 0; i < 8; i++)
        #pragma unroll
        for (int j = 0; j < 8; j++) acc[i][j] = 0.f;

    for (int k0 = 0; k0 < K; k0 += 16) {
        #pragma unroll
        for (int l = 0; l < 2; l++) {
            int r = lrow + l*64;
            float4 av = *(const float4*)(A + (size_t)(bm+r)*K + k0 + lk);
            As[lk+0][r]=av.x; As[lk+1][r]=av.y; As[lk+2][r]=av.z; As[lk+3][r]=av.w;
            float4 wv = *(const float4*)(W + (size_t)(bn+r)*K + k0 + lk);
            Bs[lk+0][r]=wv.x; Bs[lk+1][r]=wv.y; Bs[lk+2][r]=wv.z; Bs[lk+3][r]=wv.w;
        }
        __syncthreads();
        #pragma unroll
        for (int k = 0; k < 16; k++) {
            float4 a0 = *(const float4*)&As[k][ty*8];
            float4 a1 = *(const float4*)&As[k][ty*8+4];
            float4 b0 = *(const float4*)&Bs[k][tx*8];
            float4 b1 = *(const float4*)&Bs[k][tx*8+4];
            float ra[8] = {a0.x,a0.y,a0.z,a0.w,a1.x,a1.y,a1.z,a1.w};
            float rb[8] = {b0.x,b0.y,b0.z,b0.w,b1.x,b1.y,b1.z,b1.w};
            #pragma unroll
            for (int i = 0; i < 8; i++)
                #pragma unroll
                for (int j = 0; j < 8; j++) acc[i][j] += ra[i]*rb[j];
        }
        __syncthreads();
    }

    if (U) {  // rank-16 LoRA epilogue (one extra K=16 tile)
        #pragma unroll
        for (int l = 0; l < 2; l++) {
            int r = lrow + l*64;
            float4 uv = *(const float4*)(U + (size_t)(bm+r)*16 + lk);
            As[lk+0][r]=uv.x; As[lk+1][r]=uv.y; As[lk+2][r]=uv.z; As[lk+3][r]=uv.w;
            float4 vv = *(const float4*)(V + (size_t)(bn+r)*16 + lk);
            Bs[lk+0][r]=vv.x; Bs[lk+1][r]=vv.y; Bs[lk+2][r]=vv.z; Bs[lk+3][r]=vv.w;
        }
        __syncthreads();
        #pragma unroll
        for (int k = 0; k < 16; k++) {
            float4 a0 = *(const float4*)&As[k][ty*8];
            float4 a1 = *(const float4*)&As[k][ty*8+4];
            float4 b0 = *(const float4*)&Bs[k][tx*8];
            float4 b1 = *(const float4*)&Bs[k][tx*8+4];
            float ra[8] = {a0.x,a0.y,a0.z,a0.w,a1.x,a1.y,a1.z,a1.w};
            float rb[8] = {b0.x,b0.y,b0.z,b0.w,b1.x,b1.y,b1.z,b1.w};
            #pragma unroll
            for (int i = 0; i < 8; i++) {
                float sa = lscale*ra[i];
                #pragma unroll
                for (int j = 0; j < 8; j++) acc[i][j] += sa*rb[j];
            }
        }
    }

    #pragma unroll
    for (int i = 0; i < 8; i++) {
        size_t m = (size_t)(bm + ty*8 + i);
        #pragma unroll
        for (int j = 0; j < 8; j += 4) {
            size_t n = (size_t)(bn + tx*8 + j);
            float4 o;
            o.x=acc[i][j]; o.y=acc[i][j+1]; o.z=acc[i][j+2]; o.w=acc[i][j+3];
            if (res) {
                float4 rr = *(const float4*)(res + m*N + n);
                o.x+=rr.x; o.y+=rr.y; o.z+=rr.z; o.w+=rr.w;
            }
            *(float4*)(C + m*N + n) = o;
        }
    }
}

// ---------------------------------------------------------------------------
// RoPE (in place), interleaved-pair convention
// ---------------------------------------------------------------------------
__global__ void k_rope(float* __restrict__ x, const float* __restrict__ cs,
                       const float* __restrict__ sn, int nh, int total) {
    int i = blockIdx.x*256 + threadIdx.x;
    if (i >= total) return;
    int d2 = i & 63;
    int h  = (i >> 6) % nh;
    int t  = i / (64*nh);
    int s  = t & (CK_S - 1);
    float c  = cs[s*64 + d2];
    float si = sn[s*64 + d2];
    float* p = x + ((size_t)t*nh + h)*CK_HD + 2*d2;
    float x1 = p[0], x2 = p[1];
    p[0] = x1*c - x2*si;
    p[1] = x1*si + x2*c;
}

// ---------------------------------------------------------------------------
// scores[bh,s,t] = (q_s . k_t) / sqrt(HD) (upper-triangle tiles skipped)
// 64x64 tiles, K=128
// ---------------------------------------------------------------------------
__global__ void __launch_bounds__(256) k_scores(const float* __restrict__ xq,
                                                const float* __restrict__ xk,
                                                float* __restrict__ sc) {
    const int t0 = blockIdx.x*64, s0 = blockIdx.y*64;
    if (t0 > s0 + 63) return;
    const int bh = blockIdx.z, b = bh >> 4, h = bh & 15, kv = h >> 2;
    const float* Q  = xq + ((size_t)b*CK_S*CK_H  + h )*CK_HD;
    const float* Kp = xk + ((size_t)b*CK_S*CK_KV + kv)*CK_HD;
    __shared__ float Qs[16][64], Ks[16][64];
    const int tid = threadIdx.x;
    const int lrow = tid >> 2, lk = (tid & 3)*4;
    const int ty = tid >> 4, tx = tid & 15;
    float acc[4][4];
    #pragma unroll
    for (int i=0;i<4;i++)
        #pragma unroll
        for (int j=0;j<4;j++) acc[i][j]=0.f;

    for (int k0 = 0; k0 < CK_HD; k0 += 16) {
        float4 q4 = *(const float4*)(Q  + (size_t)(s0+lrow)*(CK_H*CK_HD)  + k0 + lk);
        Qs[lk+0][lrow]=q4.x; Qs[lk+1][lrow]=q4.y; Qs[lk+2][lrow]=q4.z; Qs[lk+3][lrow]=q4.w;
        float4 k4 = *(const float4*)(Kp + (size_t)(t0+lrow)*(CK_KV*CK_HD) + k0 + lk);
        Ks[lk+0][lrow]=k4.x; Ks[lk+1][lrow]=k4.y; Ks[lk+2][lrow]=k4.z; Ks[lk+3][lrow]=k4.w;
        __syncthreads();
        #pragma unroll
        for (int k = 0; k < 16; k++) {
            float4 a  = *(const float4*)&Qs[k][ty*4];
            float4 bb = *(const float4*)&Ks[k][tx*4];
            float ra[4] = {a.x,a.y,a.z,a.w};
            float rb[4] = {bb.x,bb.y,bb.z,bb.w};
            #pragma unroll
            for (int i=0;i<4;i++)
                #pragma unroll
                for (int j=0;j<4;j++) acc[i][j] += ra[i]*rb[j];
        }
        __syncthreads();
    }
    const float scl = 0.08838834764831845f;   // 1/sqrt(128)
    float* out = sc + (size_t)bh*CK_S*CK_S;
    #pragma unroll
    for (int i = 0; i < 4; i++) {
        size_t srow = (size_t)(s0 + ty*4 + i);
        float4 o;
        o.x=acc[i][0]*scl; o.y=acc[i][1]*scl; o.z=acc[i][2]*scl; o.w=acc[i][3]*scl;
        *(float4*)(out + srow*CK_S + t0 + tx*4) = o;
    }
}

// ---------------------------------------------------------------------------
// Causal softmax in place; writes zeros for t > s
// ---------------------------------------------------------------------------
__global__ void k_softmax(float* __restrict__ sc) {
    int row = blockIdx.x;            // bh*512 + s
    int s = row & (CK_S - 1);
    float* p = sc + (size_t)row*CK_S;
    int L = s + 1;
    int tid = threadIdx.x;
    __shared__ float red[256];
    float m = -1e30f;
    for (int i = tid; i < L; i += 256) m = fmaxf(m, p[i]);
    red[tid] = m; __syncthreads();
    for (int st = 128; st; st >>= 1) {
        if (tid < st) red[tid] = fmaxf(red[tid], red[tid+st]);
        __syncthreads();
    }
    m = red[0]; __syncthreads();
    float sum = 0.f;
    for (int i = tid; i < L; i += 256) { float e = expf(p[i]-m); p[i] = e; sum += e; }
    red[tid] = sum; __syncthreads();
    for (int st = 128; st; st >>= 1) {
        if (tid < st) red[tid] += red[tid+st];
        __syncthreads();
    }
    float inv = 1.f/red[0];
    for (int i = tid;     i < L;    i += 256) p[i] *= inv;
    for (int i = L + tid; i < CK_S; i += 256) p[i] = 0.f;
}

// ---------------------------------------------------------------------------
// out[b,s,h,:] = attn[bh,s,:] @ V[b,:,kv,:]  (64x128 tile, K=512)
// ---------------------------------------------------------------------------
__global__ void __launch_bounds__(256) k_av(const float* __restrict__ attn,
                                            const float* __restrict__ xv,
                                            float* __restrict__ out) {
    const int s0 = blockIdx.x*64;
    const int bh = blockIdx.z, b = bh >> 4, h = bh & 15, kv = h >> 2;
    const float* Ab = attn + (size_t)bh*CK_S*CK_S;
    const float* Vb = xv + ((size_t)b*CK_S*CK_KV + kv)*CK_HD;
    __shared__ float As[64][33];
    __shared__ float Vs[32][128];
    const int tid = threadIdx.x;
    const int ty = tid >> 5, tx = tid & 31;
    float acc[8][4];
    #pragma unroll
    for (int i=0;i<8;i++)
        #pragma unroll
        for (int j=0;j<4;j++) acc[i][j]=0.f;

    for (int k0 = 0; k0 < CK_S; k0 += 32) {
        #pragma unroll
        for (int l = 0; l < 2; l++) {
            int id = tid + l*256, r = id >> 3, c4 = (id & 7)*4;
            float4 a = *(const float4*)(Ab + (size_t)(s0+r)*CK_S + k0 + c4);
            As[r][c4]=a.x; As[r][c4+1]=a.y; As[r][c4+2]=a.z; As[r][c4+3]=a.w;
        }
        #pragma unroll
        for (int l = 0; l < 4; l++) {
            int id = tid + l*256, r = id >> 5, c4 = (id & 31)*4;
            float4 v = *(const float4*)(Vb + (size_t)(k0+r)*(CK_KV*CK_HD) + c4);
            *(float4*)&Vs[r][c4] = v;
        }
        __syncthreads();
        #pragma unroll
        for (int k = 0; k < 32; k++) {
            float4 vv = *(const float4*)&Vs[k][tx*4];
            #pragma unroll
            for (int i = 0; i < 8; i++) {
                float a = As[ty*8+i][k];
                acc[i][0]+=a*vv.x; acc[i][1]+=a*vv.y; acc[i][2]+=a*vv.z; acc[i][3]+=a*vv.w;
            }
        }
        __syncthreads();
    }
    #pragma unroll
    for (int i = 0; i < 8; i++) {
        int s = s0 + ty*8 + i;
        float4 o; o.x=acc[i][0]; o.y=acc[i][1]; o.z=acc[i][2]; o.w=acc[i][3];
        *(float4*)(out + ((size_t)(b*CK_S+s)*CK_H + h)*CK_HD + tx*4) = o;
    }
}

// ---------------------------------------------------------------------------
// Gate: logits -> softmax -> top2 -> normalized route row (one block / token)
// ---------------------------------------------------------------------------
__global__ void k_gate(const float* __restrict__ hn, const float* __restrict__ gw,
                       float* __restrict__ route) {
    int t = blockIdx.x;
    __shared__ float sl[8];
    int w = threadIdx.x >> 5, lane = threadIdx.x & 31;
    const float* xr = hn + (size_t)t*CK_D;
    const float* gr = gw + (size_t)w*CK_D;
    float p = 0.f;
    for (int d = lane; d < CK_D; d += 32) p += xr[d]*gr[d];
    for (int o = 16; o; o >>= 1) p += __shfl_down_sync(0xffffffffu, p, o);
    if (lane == 0) sl[w] = p;
    __syncthreads();
    if (threadIdx.x == 0) {
        int i0 = 0;
        for (int e = 1; e < 8; e++) if (sl[e] > sl[i0]) i0 = e;
        int i1 = -1;
        for (int e = 0; e < 8; e++) { if (e == i0) continue; if (i1 < 0 || sl[e] > sl[i1]) i1 = e; }
        float m = sl[i0];
        float v0 = expf(sl[i0]-m), v1 = expf(sl[i1]-m);
        float inv = 1.f/(v0+v1);
        float* rr = route + (size_t)t*CK_E;
        #pragma unroll
        for (int e = 0; e < 8; e++) rr[e] = 0.f;
        rr[i0] = v0*inv; rr[i1] = v1*inv;
    }
}

// ---------------------------------------------------------------------------
// Expert LoRA downs: ua1/ua3[t,e,r]; skips inactive (t,e)
// ---------------------------------------------------------------------------
__global__ void k_expert_down(const float* __restrict__ X, const float* __restrict__ A1,
                              const float* __restrict__ A3, const float* __restrict__ route,
                              float* __restrict__ U1, float* __restrict__ U3) {
    int t = blockIdx.x, e = blockIdx.y;
    if (route[t*CK_E + e] == 0.f) return;
    __shared__ float sx[CK_D];
    for (int i = threadIdx.x; i < CK_D; i += 256) sx[i] = X[(size_t)t*CK_D + i];
    __syncthreads();
    int w = threadIdx.x >> 5, lane = threadIdx.x & 31;
    const float* a1 = A1 + (size_t)e*CK_R*CK_D;
    const float* a3 = A3 + (size_t)e*CK_R*CK_D;
    for (int r = w; r < CK_R; r += 8) {
        float p1 = 0.f, p3 = 0.f;
        for (int d = lane; d < CK_D; d += 32) {
            float xv = sx[d];
            p1 += xv*a1[(size_t)r*CK_D + d];
            p3 += xv*a3[(size_t)r*CK_D + d];
        }
        for (int o = 16; o; o >>= 1) {
            p1 += __shfl_down_sync(0xffffffffu, p1, o);
            p3 += __shfl_down_sync(0xffffffffu, p3, o);
        }
        if (lane == 0) {
            U1[((size_t)t*CK_E + e)*CK_R + r] = p1;
            U3[((size_t)t*CK_E + e)*CK_R + r] = p3;
        }
    }
}

// ---------------------------------------------------------------------------
// Fused per-token MoE: ghsum[t,:] = sum_e w_e * gh_e,  v2[t,e*16+r] =
// w_e*LS*(gh_e . eA2[e][r,:]).  Block per token; inactive experts skipped.
// ---------------------------------------------------------------------------
__global__ void __launch_bounds__(256) k_moe_expert(
    const float* __restrict__ h1, const float* __restrict__ h3,
    const float* __restrict__ ua1, const float* __restrict__ ua3,
    const float* __restrict__ eB1, const float* __restrict__ eB3,
    const float* __restrict__ eA2, const float* __restrict__ route,
    float* __restrict__ ghs, float* __restrict__ v2)
{
    const int t = blockIdx.x;
    const int tid = threadIdx.x;
    const int wid = tid >> 5, lane = tid & 31;
    const int NI = CK_FFN/256;   // 22
    float ghacc[CK_FFN/256];
    #pragma unroll
    for (int i = 0; i < NI; i++) ghacc[i] = 0.f;
    __shared__ float su1[16], su3[16];
    __shared__ float part[8][16];
    const float* h1r = h1 + (size_t)t*CK_FFN;
    const float* h3r = h3 + (size_t)t*CK_FFN;

    #pragma unroll 1
    for (int e = 0; e < CK_E; e++) {
        float wgt = route[t*CK_E + e];
        if (wgt == 0.f) {
            if (tid < 16) v2[(size_t)t*(CK_E*CK_R) + e*16 + tid] = 0.f;
            continue;
        }
        if (tid < 16) {
            su1[tid] = ua1[((size_t)t*CK_E + e)*16 + tid];
            su3[tid] = ua3[((size_t)t*CK_E + e)*16 + tid];
        }
        __syncthreads();
        float u1[16], u3[16];
        #pragma unroll
        for (int r = 0; r < 16; r++) { u1[r] = su1[r]; u3[r] = su3[r]; }
        float accr[16];
        #pragma unroll
        for (int r = 0; r < 16; r++) accr[r] = 0.f;
        const float* B1 = eB1 + (size_t)e*CK_FFN*16;
        const float* B3 = eB3 + (size_t)e*CK_FFN*16;
        const float* A2 = eA2 + (size_t)e*16*CK_FFN;
        #pragma unroll
        for (int ii = 0; ii < NI; ii++) {
            int f = ii*256 + tid;
            const float4* b1p = (const float4*)(B1 + (size_t)f*16);
            const float4* b3p = (const float4*)(B3 + (size_t)f*16);
            float b1 = 0.f, b3 = 0.f;
            #pragma unroll
            for (int q = 0; q < 4; q++) {
                float4 x1 = b1p[q], x3 = b3p[q];
                b1 += u1[q*4+0]*x1.x + u1[q*4+1]*x1.y + u1[q*4+2]*x1.z + u1[q*4+3]*x1.w;
                b3 += u3[q*4+0]*x3.x + u3[q*4+1]*x3.y + u3[q*4+2]*x3.z + u3[q*4+3]*x3.w;
            }
            float g1 = h1r[f] + CK_LS*b1;
            float g3 = h3r[f] + CK_LS*b3;
            float gh = (g1/(1.f + expf(-g1)))*g3;   // silu(g1)*g3
            ghacc[ii] += wgt*gh;
            #pragma unroll
            for (int r = 0; r < 16; r++) accr[r] += gh * A2[(size_t)r*CK_FFN + f];
        }
        #pragma unroll
        for (int r = 0; r < 16; r++) {
            float v = accr[r];
            #pragma unroll
            for (int o = 16; o; o >>= 1) v += __shfl_down_sync(0xffffffffu, v, o);
            if (lane == 0) part[wid][r] = v;
        }
        __syncthreads();
        if (tid < 16) {
            float s2 = 0.f;
            #pragma unroll
            for (int ww = 0; ww < 8; ww++) s2 += part[ww][tid];
            v2[(size_t)t*(CK_E*CK_R) + e*16 + tid] = wgt*CK_LS*s2;
        }
        __syncthreads();
    }
    float* go = ghs + (size_t)t*CK_FFN;
    #pragma unroll
    for (int ii = 0; ii < NI; ii++) go[ii*256 + tid] = ghacc[ii];
}

// ---------------------------------------------------------------------------
// fpre[t,d] = data2[t,d] + sum_{e,r} v2[t,e*16+r] * eB2[e][d][r]
// ---------------------------------------------------------------------------
__global__ void k_moe_up(const float* __restrict__ d2, const float* __restrict__ v2,
                         const float* __restrict__ eB2, const float* __restrict__ route,
                         float* __restrict__ out) {
    int t = blockIdx.x, tid = threadIdx.x;
    __shared__ float sv[128];
    __shared__ int act[8];
    if (tid < 128) sv[tid] = v2[(size_t)t*128 + tid];
    if (tid < 8)   act[tid] = (route[t*CK_E + tid] != 0.f) ? 1 : 0;
    __syncthreads();
    for (int d = tid; d < CK_D; d += 256) {
        float s = d2[(size_t)t*CK_D + d];
        #pragma unroll 1
        for (int e = 0; e < 8; e++) {
            if (!act[e]) continue;
            const float4* bp = (const float4*)(eB2 + ((size_t)e*CK_D + d)*16);
            #pragma unroll
            for (int q = 0; q < 4; q++) {
                float4 bb = bp[q];
                s += sv[e*16+q*4+0]*bb.x + sv[e*16+q*4+1]*bb.y
                   + sv[e*16+q*4+2]*bb.z + sv[e*16+q*4+3]*bb.w;
            }
        }
        out[(size_t)t*CK_D + d] = s;
    }
}

// ---------------------------------------------------------------------------
// Launch
// ---------------------------------------------------------------------------
extern "C" void kernel_launch(void* const* d_in, const int* in_sizes, int n_in,
                              void* d_out, int out_size) {
    (void)in_sizes; (void)n_in; (void)out_size;
    const float* data  = (const float*)d_in[0];
    const float* rc    = (const float*)d_in[2];
    const float* rs    = (const float*)d_in[3];
    const float* att_w = (const float*)d_in[4];
    const float* ffn_w = (const float*)d_in[5];
    const float* wq    = (const float*)d_in[6];
    const float* wk    = (const float*)d_in[7];
    const float* wv    = (const float*)d_in[8];
    const float* wo    = (const float*)d_in[9];
    const float* lqA   = (const float*)d_in[10];
    const float* lqB   = (const float*)d_in[11];
    const float* lkA   = (const float*)d_in[12];
    const float* lkB   = (const float*)d_in[13];
    const float* lvA   = (const float*)d_in[14];
    const float* lvB   = (const float*)d_in[15];
    const float* loA   = (const float*)d_in[16];
    const float* loB   = (const float*)d_in[17];
    const float* w1    = (const float*)d_in[18];
    const float* w2    = (const float*)d_in[19];
    const float* w3    = (const float*)d_in[20];
    const float* gatew = (const float*)d_in[21];
    const float* eA1   = (const float*)d_in[22];
    const float* eB1   = (const float*)d_in[23];
    const float* eA2   = (const float*)d_in[24];
    const float* eB2   = (const float*)d_in[25];
    const float* eA3   = (const float*)d_in[26];
    const float* eB3   = (const float*)d_in[27];
    float* out = (float*)d_out;

    float *p_h,*p_hn,*p_xq,*p_xk,*p_xv,*p_sc,*p_ao,*p_d2,*p_uq,*p_uk,*p_uv,*p_uo;
    float *p_route,*p_ua1,*p_ua3,*p_h1,*p_h3,*p_ghs,*p_v2,*p_fpre;
    cudaGetSymbolAddress((void**)&p_h,    g_h);
    cudaGetSymbolAddress((void**)&p_hn,   g_hn);
    cudaGetSymbolAddress((void**)&p_xq,   g_xq);
    cudaGetSymbolAddress((void**)&p_xk,   g_xk);
    cudaGetSymbolAddress((void**)&p_xv,   g_xv);
    cudaGetSymbolAddress((void**)&p_sc,   g_sc);
    cudaGetSymbolAddress((void**)&p_ao,   g_ao);
    cudaGetSymbolAddress((void**)&p_d2,   g_d2);
    cudaGetSymbolAddress((void**)&p_uq,   g_uq);
    cudaGetSymbolAddress((void**)&p_uk,   g_uk);
    cudaGetSymbolAddress((void**)&p_uv,   g_uv);
    cudaGetSymbolAddress((void**)&p_uo,   g_uo);
    cudaGetSymbolAddress((void**)&p_route,g_route);
    cudaGetSymbolAddress((void**)&p_ua1,  g_ua1);
    cudaGetSymbolAddress((void**)&p_ua3,  g_ua3);
    cudaGetSymbolAddress((void**)&p_h1,   g_h1);
    cudaGetSymbolAddress((void**)&p_h3,   g_h3);
    cudaGetSymbolAddress((void**)&p_ghs,  g_ghs);
    cudaGetSymbolAddress((void**)&p_v2,   g_v2);
    cudaGetSymbolAddress((void**)&p_fpre, g_fpre);

    // --- attention path ---
    k_rmsnorm<<<CK_T,256>>>(data, att_w, p_h);
    k_lora_down<<<CK_T,256>>>(p_h, lqA, p_uq);
    k_lora_down<<<CK_T,256>>>(p_h, lkA, p_uk);
    k_lora_down<<<CK_T,256>>>(p_h, lvA, p_uv);
    k_sgemm<<<dim3(CK_D/128,  CK_T/128),256>>>(p_h, wq, p_xq, CK_T, CK_D, CK_D, p_uq, lqB, CK_LS, nullptr);
    k_sgemm<<<dim3(512/128,   CK_T/128),256>>>(p_h, wk, p_xk, CK_T, 512,  CK_D, p_uk, lkB, CK_LS, nullptr);
    k_sgemm<<<dim3(512/128,   CK_T/128),256>>>(p_h, wv, p_xv, CK_T, 512,  CK_D, p_uv, lvB, CK_LS, nullptr);
    k_rope<<<(CK_T*CK_H*64 + 255)/256, 256>>>(p_xq, rc, rs, CK_H,  CK_T*CK_H*64);
    k_rope<<<(CK_T*CK_KV*64 + 255)/256,256>>>(p_xk, rc, rs, CK_KV, CK_T*CK_KV*64);
    k_scores<<<dim3(CK_S/64, CK_S/64, CK_B*CK_H),256>>>(p_xq, p_xk, p_sc);
    k_softmax<<<CK_B*CK_H*CK_S,256>>>(p_sc);
    k_av<<<dim3(CK_S/64, 1, CK_B*CK_H),256>>>(p_sc, p_xv, p_ao);
    k_lora_down<<<CK_T,256>>>(p_ao, loA, p_uo);
    k_sgemm<<<dim3(CK_D/128, CK_T/128),256>>>(p_ao, wo, p_d2, CK_T, CK_D, CK_D, p_uo, loB, CK_LS, data);

    // --- MoE path ---
    k_rmsnorm<<<CK_T,256>>>(p_d2, ffn_w, p_hn);
    k_gate<<<CK_T,256>>>(p_hn, gatew, p_route);
    k_expert_down<<<dim3(CK_T, CK_E),256>>>(p_hn, eA1, eA3, p_route, p_ua1, p_ua3);
    k_sgemm<<<dim3(CK_FFN/128, CK_T/128),256>>>(p_hn, w1, p_h1, CK_T, CK_FFN, CK_D, nullptr, nullptr, 0.f, nullptr);
    k_sgemm<<<dim3(CK_FFN/128, CK_T/128),256>>>(p_hn, w3, p_h3, CK_T, CK_FFN, CK_D, nullptr, nullptr, 0.f, nullptr);
    k_moe_expert<<<CK_T,256>>>(p_h1, p_h3, p_ua1, p_ua3, eB1, eB3, eA2, p_route, p_ghs, p_v2);
    k_moe_up<<<CK_T,256>>>(p_d2, p_v2, eB2, p_route, p_fpre);
    k_sgemm<<<dim3(CK_D/128, CK_T/128),256>>>(p_ghs, w2, out, CK_T, CK_D, CK_FFN, nullptr, nullptr, 0.f, p_fpre);
}

// round 6
// speedup vs baseline: 1.6767x; 1.6767x over previous
#include <cuda_runtime.h>
#include <cuda_bf16.h>
#include <math.h>
#include <stdint.h>

#define CK_B   4
#define CK_S   512
#define CK_D   2048
#define CK_H   16
#define CK_KV  4
#define CK_HD  128
#define CK_T   2048          // B*S
#define CK_FFN 5632
#define CK_E   8
#define CK_R   16
#define CK_LS  2.0f          // 32/16

// ---------------------------------------------------------------------------
// Scratch (static device arrays — allocation-free, graph-safe)
// ---------------------------------------------------------------------------
__device__ float g_h   [CK_T*CK_D];
__device__ float g_hn  [CK_T*CK_D];
__device__ float g_xq  [CK_T*CK_D];
__device__ float g_xk  [CK_T*CK_KV*CK_HD];
__device__ float g_xv  [CK_T*CK_KV*CK_HD];
__device__ float g_sc  [(size_t)CK_B*CK_H*CK_S*CK_S];
__device__ float g_ao  [CK_T*CK_D];
__device__ float g_d2  [CK_T*CK_D];
__device__ float g_uq  [CK_T*CK_R];
__device__ float g_uk  [CK_T*CK_R];
__device__ float g_uv  [CK_T*CK_R];
__device__ float g_uo  [CK_T*CK_R];
__device__ float g_route[CK_T*CK_E];
__device__ float g_ua1 [CK_T*CK_E*CK_R];
__device__ float g_ua3 [CK_T*CK_E*CK_R];
__device__ float g_h1  [(size_t)CK_T*CK_FFN];
__device__ float g_h3  [(size_t)CK_T*CK_FFN];
__device__ float g_ghs [(size_t)CK_T*CK_FFN];
__device__ float g_v2  [CK_T*CK_E*CK_R];
__device__ float g_fpre[CK_T*CK_D];

// ===========================================================================
// bf16 split-precision GEMM via mma.sync (tensor cores, sm_80+ path — works
// under the harness's compute_103 PTX target):
//   C = A(MxK) @ W(NxK)^T [+ lscale*U(Mx16)@V(Nx16)^T] [+ res]
// fp32 operands split into hi+lo bf16; accumulate hi*hi + hi*lo + lo*hi in
// fp32 (lo*lo dropped, ~2^-17 relative).
// Tiles: 128x128x32, 256 threads (8 warps, 4x2), warp tile 32x64.
// ===========================================================================
#define HG_BM 128
#define HG_BN 128
#define HG_BK 32
#define HG_LD 40            // smem row stride in bf16 (conflict-free: bank=g*20+tg)

__device__ __forceinline__ void mma16816(float* d, const uint32_t* a,
                                         uint32_t b0, uint32_t b1) {
    asm volatile(
        "mma.sync.aligned.m16n8k16.row.col.f32.bf16.bf16.f32 "
        "{%0,%1,%2,%3}, {%4,%5,%6,%7}, {%8,%9}, {%0,%1,%2,%3};"
        : "+f"(d[0]), "+f"(d[1]), "+f"(d[2]), "+f"(d[3])
        : "r"(a[0]), "r"(a[1]), "r"(a[2]), "r"(a[3]), "r"(b0), "r"(b1));
}

__device__ __forceinline__ void split4(__nv_bfloat16* hp, __nv_bfloat16* lp, float4 v) {
    float vs[4] = {v.x, v.y, v.z, v.w};
    __nv_bfloat16 h[4], l[4];
    #pragma unroll
    for (int i = 0; i < 4; i++) {
        h[i] = __float2bfloat16(vs[i]);
        l[i] = __float2bfloat16(vs[i] - __bfloat162float(h[i]));
    }
    *(__nv_bfloat162*)(hp + 0) = __halves2bfloat162(h[0], h[1]);
    *(__nv_bfloat162*)(hp + 2) = __halves2bfloat162(h[2], h[3]);
    *(__nv_bfloat162*)(lp + 0) = __halves2bfloat162(l[0], l[1]);
    *(__nv_bfloat162*)(lp + 2) = __halves2bfloat162(l[2], l[3]);
}

__global__ void __launch_bounds__(256) k_hgemm(
    const float* __restrict__ A, const float* __restrict__ W, float* __restrict__ C,
    int M, int N, int K,
    const float* __restrict__ U, const float* __restrict__ V, float lscale,
    const float* __restrict__ res)
{
    __shared__ __nv_bfloat16 sAh[HG_BM][HG_LD];
    __shared__ __nv_bfloat16 sAl[HG_BM][HG_LD];
    __shared__ __nv_bfloat16 sWh[HG_BN][HG_LD];
    __shared__ __nv_bfloat16 sWl[HG_BN][HG_LD];

    const int tid  = threadIdx.x;
    const int wid  = tid >> 5, lane = tid & 31;
    const int g    = lane >> 2, tg = lane & 3;
    const int warpM = wid & 3;          // 4 warps over M (4*32 = 128)
    const int warpN = wid >> 2;         // 2 warps over N (2*64 = 128)
    const int bm = blockIdx.y * HG_BM;
    const int bn = blockIdx.x * HG_BN;

    float acc[2][8][4];
    #pragma unroll
    for (int mi = 0; mi < 2; mi++)
        #pragma unroll
        for (int ni = 0; ni < 8; ni++)
            #pragma unroll
            for (int q = 0; q < 4; q++) acc[mi][ni][q] = 0.f;

    const int NC = K / HG_BK;
    const int total = NC + (U ? 1 : 0);

    for (int c = 0; c < total; c++) {
        // ---- stage tiles into smem (hi/lo split) ----
        if (c < NC) {
            const int k0 = c * HG_BK;
            #pragma unroll
            for (int l = 0; l < 4; l++) {
                int id = l*256 + tid;
                int r  = id >> 3, c4 = (id & 7) * 4;
                float4 va = *(const float4*)(A + (size_t)(bm + r)*K + k0 + c4);
                split4(&sAh[r][c4], &sAl[r][c4], va);
                float4 vw = *(const float4*)(W + (size_t)(bn + r)*K + k0 + c4);
                split4(&sWh[r][c4], &sWl[r][c4], vw);
            }
        } else {
            // LoRA chunk: K=16 real, zero-padded to 32; lscale folded into U
            #pragma unroll
            for (int l = 0; l < 4; l++) {
                int id = l*256 + tid;
                int r  = id >> 3, c4 = (id & 7) * 4;
                float4 va = make_float4(0.f,0.f,0.f,0.f);
                float4 vw = make_float4(0.f,0.f,0.f,0.f);
                if (c4 < 16) {
                    va = *(const float4*)(U + (size_t)(bm + r)*16 + c4);
                    va.x *= lscale; va.y *= lscale; va.z *= lscale; va.w *= lscale;
                    vw = *(const float4*)(V + (size_t)(bn + r)*16 + c4);
                }
                split4(&sAh[r][c4], &sAl[r][c4], va);
                split4(&sWh[r][c4], &sWl[r][c4], vw);
            }
        }
        __syncthreads();

        // ---- compute: 2 k-steps of 16 ----
        #pragma unroll
        for (int ks = 0; ks < 2; ks++) {
            const int col0 = ks*16 + tg*2;
            uint32_t ah[2][4], al[2][4];
            #pragma unroll
            for (int mi = 0; mi < 2; mi++) {
                int r0 = warpM*32 + mi*16 + g;
                ah[mi][0] = *(const uint32_t*)&sAh[r0  ][col0  ];
                ah[mi][1] = *(const uint32_t*)&sAh[r0+8][col0  ];
                ah[mi][2] = *(const uint32_t*)&sAh[r0  ][col0+8];
                ah[mi][3] = *(const uint32_t*)&sAh[r0+8][col0+8];
                al[mi][0] = *(const uint32_t*)&sAl[r0  ][col0  ];
                al[mi][1] = *(const uint32_t*)&sAl[r0+8][col0  ];
                al[mi][2] = *(const uint32_t*)&sAl[r0  ][col0+8];
                al[mi][3] = *(const uint32_t*)&sAl[r0+8][col0+8];
            }
            #pragma unroll
            for (int ni = 0; ni < 8; ni++) {
                int rn = warpN*64 + ni*8 + g;
                uint32_t bh0 = *(const uint32_t*)&sWh[rn][col0  ];
                uint32_t bh1 = *(const uint32_t*)&sWh[rn][col0+8];
                uint32_t bl0 = *(const uint32_t*)&sWl[rn][col0  ];
                uint32_t bl1 = *(const uint32_t*)&sWl[rn][col0+8];
                #pragma unroll
                for (int mi = 0; mi < 2; mi++) {
                    mma16816(acc[mi][ni], ah[mi], bh0, bh1);
                    mma16816(acc[mi][ni], ah[mi], bl0, bl1);
                    mma16816(acc[mi][ni], al[mi], bh0, bh1);
                }
            }
        }
        __syncthreads();
    }

    // ---- epilogue: each thread owns 2 rows x 2 cols per (mi,ni) ----
    #pragma unroll
    for (int mi = 0; mi < 2; mi++) {
        size_t r0 = (size_t)(bm + warpM*32 + mi*16 + g);
        #pragma unroll
        for (int ni = 0; ni < 8; ni++) {
            size_t c0 = (size_t)(bn + warpN*64 + ni*8 + tg*2);
            float2 o0 = make_float2(acc[mi][ni][0], acc[mi][ni][1]);
            float2 o1 = make_float2(acc[mi][ni][2], acc[mi][ni][3]);
            if (res) {
                float2 r0v = *(const float2*)(res + r0*N + c0);
                float2 r1v = *(const float2*)(res + (r0+8)*N + c0);
                o0.x += r0v.x; o0.y += r0v.y;
                o1.x += r1v.x; o1.y += r1v.y;
            }
            *(float2*)(C + r0*N + c0)     = o0;
            *(float2*)(C + (r0+8)*N + c0) = o1;
        }
    }
}

// ---------------------------------------------------------------------------
// RMSNorm: one block per token
// ---------------------------------------------------------------------------
__global__ void k_rmsnorm(const float* __restrict__ x, const float* __restrict__ w,
                          float* __restrict__ o) {
    int t = blockIdx.x;
    const float* xr = x + (size_t)t*CK_D;
    float ss = 0.f;
    for (int i = threadIdx.x; i < CK_D; i += 256) { float v = xr[i]; ss += v*v; }
    __shared__ float red[256];
    red[threadIdx.x] = ss; __syncthreads();
    for (int s = 128; s > 0; s >>= 1) {
        if (threadIdx.x < s) red[threadIdx.x] += red[threadIdx.x+s];
        __syncthreads();
    }
    float sc = rsqrtf(red[0]/(float)CK_D + 1e-5f);
    float* orow = o + (size_t)t*CK_D;
    for (int i = threadIdx.x; i < CK_D; i += 256) orow[i] = xr[i]*sc*w[i];
}

// ---------------------------------------------------------------------------
// LoRA down-projection: U[t,r] = sum_d X[t,d]*A[r,d]
// ---------------------------------------------------------------------------
__global__ void k_lora_down(const float* __restrict__ X, const float* __restrict__ A,
                            float* __restrict__ U) {
    int t = blockIdx.x;
    __shared__ float sx[CK_D];
    for (int i = threadIdx.x; i < CK_D; i += 256) sx[i] = X[(size_t)t*CK_D + i];
    __syncthreads();
    int w = threadIdx.x >> 5, lane = threadIdx.x & 31;
    for (int r = w; r < CK_R; r += 8) {
        const float* ar = A + (size_t)r*CK_D;
        float p = 0.f;
        for (int d = lane; d < CK_D; d += 32) p += sx[d]*ar[d];
        for (int o = 16; o; o >>= 1) p += __shfl_down_sync(0xffffffffu, p, o);
        if (lane == 0) U[t*CK_R + r] = p;
    }
}

// ---------------------------------------------------------------------------
// RoPE (in place), interleaved-pair convention
// ---------------------------------------------------------------------------
__global__ void k_rope(float* __restrict__ x, const float* __restrict__ cs,
                       const float* __restrict__ sn, int nh, int total) {
    int i = blockIdx.x*256 + threadIdx.x;
    if (i >= total) return;
    int d2 = i & 63;
    int h  = (i >> 6) % nh;
    int t  = i / (64*nh);
    int s  = t & (CK_S - 1);
    float c  = cs[s*64 + d2];
    float si = sn[s*64 + d2];
    float* p = x + ((size_t)t*nh + h)*CK_HD + 2*d2;
    float x1 = p[0], x2 = p[1];
    p[0] = x1*c - x2*si;
    p[1] = x1*si + x2*c;
}

// ---------------------------------------------------------------------------
// scores[bh,s,t] = (q_s . k_t) / sqrt(HD)  (upper-triangle tiles skipped)
// ---------------------------------------------------------------------------
__global__ void __launch_bounds__(256) k_scores(const float* __restrict__ xq,
                                                const float* __restrict__ xk,
                                                float* __restrict__ sc) {
    const int t0 = blockIdx.x*64, s0 = blockIdx.y*64;
    if (t0 > s0 + 63) return;
    const int bh = blockIdx.z, b = bh >> 4, h = bh & 15, kv = h >> 2;
    const float* Q  = xq + ((size_t)b*CK_S*CK_H  + h )*CK_HD;
    const float* Kp = xk + ((size_t)b*CK_S*CK_KV + kv)*CK_HD;
    __shared__ float Qs[16][64], Ks[16][64];
    const int tid = threadIdx.x;
    const int lrow = tid >> 2, lk = (tid & 3)*4;
    const int ty = tid >> 4, tx = tid & 15;
    float acc[4][4];
    #pragma unroll
    for (int i=0;i<4;i++)
        #pragma unroll
        for (int j=0;j<4;j++) acc[i][j]=0.f;

    for (int k0 = 0; k0 < CK_HD; k0 += 16) {
        float4 q4 = *(const float4*)(Q  + (size_t)(s0+lrow)*(CK_H*CK_HD)  + k0 + lk);
        Qs[lk+0][lrow]=q4.x; Qs[lk+1][lrow]=q4.y; Qs[lk+2][lrow]=q4.z; Qs[lk+3][lrow]=q4.w;
        float4 k4 = *(const float4*)(Kp + (size_t)(t0+lrow)*(CK_KV*CK_HD) + k0 + lk);
        Ks[lk+0][lrow]=k4.x; Ks[lk+1][lrow]=k4.y; Ks[lk+2][lrow]=k4.z; Ks[lk+3][lrow]=k4.w;
        __syncthreads();
        #pragma unroll
        for (int k = 0; k < 16; k++) {
            float4 a  = *(const float4*)&Qs[k][ty*4];
            float4 bb = *(const float4*)&Ks[k][tx*4];
            float ra[4] = {a.x,a.y,a.z,a.w};
            float rb[4] = {bb.x,bb.y,bb.z,bb.w};
            #pragma unroll
            for (int i=0;i<4;i++)
                #pragma unroll
                for (int j=0;j<4;j++) acc[i][j] += ra[i]*rb[j];
        }
        __syncthreads();
    }
    const float scl = 0.08838834764831845f;   // 1/sqrt(128)
    float* out = sc + (size_t)bh*CK_S*CK_S;
    #pragma unroll
    for (int i = 0; i < 4; i++) {
        size_t srow = (size_t)(s0 + ty*4 + i);
        float4 o;
        o.x=acc[i][0]*scl; o.y=acc[i][1]*scl; o.z=acc[i][2]*scl; o.w=acc[i][3]*scl;
        *(float4*)(out + srow*CK_S + t0 + tx*4) = o;
    }
}

// ---------------------------------------------------------------------------
// Causal softmax in place; writes zeros for t > s
// ---------------------------------------------------------------------------
__global__ void k_softmax(float* __restrict__ sc) {
    int row = blockIdx.x;            // bh*512 + s
    int s = row & (CK_S - 1);
    float* p = sc + (size_t)row*CK_S;
    int L = s + 1;
    int tid = threadIdx.x;
    __shared__ float red[256];
    float m = -1e30f;
    for (int i = tid; i < L; i += 256) m = fmaxf(m, p[i]);
    red[tid] = m; __syncthreads();
    for (int st = 128; st; st >>= 1) {
        if (tid < st) red[tid] = fmaxf(red[tid], red[tid+st]);
        __syncthreads();
    }
    m = red[0]; __syncthreads();
    float sum = 0.f;
    for (int i = tid; i < L; i += 256) { float e = expf(p[i]-m); p[i] = e; sum += e; }
    red[tid] = sum; __syncthreads();
    for (int st = 128; st; st >>= 1) {
        if (tid < st) red[tid] += red[tid+st];
        __syncthreads();
    }
    float inv = 1.f/red[0];
    for (int i = tid;     i < L;    i += 256) p[i] *= inv;
    for (int i = L + tid; i < CK_S; i += 256) p[i] = 0.f;
}

// ---------------------------------------------------------------------------
// out[b,s,h,:] = attn[bh,s,:] @ V[b,:,kv,:]
// ---------------------------------------------------------------------------
__global__ void __launch_bounds__(256) k_av(const float* __restrict__ attn,
                                            const float* __restrict__ xv,
                                            float* __restrict__ out) {
    const int s0 = blockIdx.x*64;
    const int bh = blockIdx.z, b = bh >> 4, h = bh & 15, kv = h >> 2;
    const float* Ab = attn + (size_t)bh*CK_S*CK_S;
    const float* Vb = xv + ((size_t)b*CK_S*CK_KV + kv)*CK_HD;
    __shared__ float As[64][33];
    __shared__ float Vs[32][128];
    const int tid = threadIdx.x;
    const int ty = tid >> 5, tx = tid & 31;
    float acc[8][4];
    #pragma unroll
    for (int i=0;i<8;i++)
        #pragma unroll
        for (int j=0;j<4;j++) acc[i][j]=0.f;

    for (int k0 = 0; k0 < CK_S; k0 += 32) {
        #pragma unroll
        for (int l = 0; l < 2; l++) {
            int id = tid + l*256, r = id >> 3, c4 = (id & 7)*4;
            float4 a = *(const float4*)(Ab + (size_t)(s0+r)*CK_S + k0 + c4);
            As[r][c4]=a.x; As[r][c4+1]=a.y; As[r][c4+2]=a.z; As[r][c4+3]=a.w;
        }
        #pragma unroll
        for (int l = 0; l < 4; l++) {
            int id = tid + l*256, r = id >> 5, c4 = (id & 31)*4;
            float4 v = *(const float4*)(Vb + (size_t)(k0+r)*(CK_KV*CK_HD) + c4);
            *(float4*)&Vs[r][c4] = v;
        }
        __syncthreads();
        #pragma unroll
        for (int k = 0; k < 32; k++) {
            float4 vv = *(const float4*)&Vs[k][tx*4];
            #pragma unroll
            for (int i = 0; i < 8; i++) {
                float a = As[ty*8+i][k];
                acc[i][0]+=a*vv.x; acc[i][1]+=a*vv.y; acc[i][2]+=a*vv.z; acc[i][3]+=a*vv.w;
            }
        }
        __syncthreads();
    }
    #pragma unroll
    for (int i = 0; i < 8; i++) {
        int s = s0 + ty*8 + i;
        float4 o; o.x=acc[i][0]; o.y=acc[i][1]; o.z=acc[i][2]; o.w=acc[i][3];
        *(float4*)(out + ((size_t)(b*CK_S+s)*CK_H + h)*CK_HD + tx*4) = o;
    }
}

// ---------------------------------------------------------------------------
// Gate: logits -> softmax -> top2 -> normalized route row
// ---------------------------------------------------------------------------
__global__ void k_gate(const float* __restrict__ hn, const float* __restrict__ gw,
                       float* __restrict__ route) {
    int t = blockIdx.x;
    __shared__ float sl[8];
    int w = threadIdx.x >> 5, lane = threadIdx.x & 31;
    const float* xr = hn + (size_t)t*CK_D;
    const float* gr = gw + (size_t)w*CK_D;
    float p = 0.f;
    for (int d = lane; d < CK_D; d += 32) p += xr[d]*gr[d];
    for (int o = 16; o; o >>= 1) p += __shfl_down_sync(0xffffffffu, p, o);
    if (lane == 0) sl[w] = p;
    __syncthreads();
    if (threadIdx.x == 0) {
        int i0 = 0;
        for (int e = 1; e < 8; e++) if (sl[e] > sl[i0]) i0 = e;
        int i1 = -1;
        for (int e = 0; e < 8; e++) { if (e == i0) continue; if (i1 < 0 || sl[e] > sl[i1]) i1 = e; }
        float m = sl[i0];
        float v0 = expf(sl[i0]-m), v1 = expf(sl[i1]-m);
        float inv = 1.f/(v0+v1);
        float* rr = route + (size_t)t*CK_E;
        #pragma unroll
        for (int e = 0; e < 8; e++) rr[e] = 0.f;
        rr[i0] = v0*inv; rr[i1] = v1*inv;
    }
}

// ---------------------------------------------------------------------------
// Expert LoRA downs: ua1/ua3[t,e,r]; skips inactive (t,e)
// ---------------------------------------------------------------------------
__global__ void k_expert_down(const float* __restrict__ X, const float* __restrict__ A1,
                              const float* __restrict__ A3, const float* __restrict__ route,
                              float* __restrict__ U1, float* __restrict__ U3) {
    int t = blockIdx.x, e = blockIdx.y;
    if (route[t*CK_E + e] == 0.f) return;
    __shared__ float sx[CK_D];
    for (int i = threadIdx.x; i < CK_D; i += 256) sx[i] = X[(size_t)t*CK_D + i];
    __syncthreads();
    int w = threadIdx.x >> 5, lane = threadIdx.x & 31;
    const float* a1 = A1 + (size_t)e*CK_R*CK_D;
    const float* a3 = A3 + (size_t)e*CK_R*CK_D;
    for (int r = w; r < CK_R; r += 8) {
        float p1 = 0.f, p3 = 0.f;
        for (int d = lane; d < CK_D; d += 32) {
            float xv = sx[d];
            p1 += xv*a1[(size_t)r*CK_D + d];
            p3 += xv*a3[(size_t)r*CK_D + d];
        }
        for (int o = 16; o; o >>= 1) {
            p1 += __shfl_down_sync(0xffffffffu, p1, o);
            p3 += __shfl_down_sync(0xffffffffu, p3, o);
        }
        if (lane == 0) {
            U1[((size_t)t*CK_E + e)*CK_R + r] = p1;
            U3[((size_t)t*CK_E + e)*CK_R + r] = p3;
        }
    }
}

// ---------------------------------------------------------------------------
// Fused per-token MoE combine (ghsum + A2 projections)
// ---------------------------------------------------------------------------
__global__ void __launch_bounds__(256) k_moe_expert(
    const float* __restrict__ h1, const float* __restrict__ h3,
    const float* __restrict__ ua1, const float* __restrict__ ua3,
    const float* __restrict__ eB1, const float* __restrict__ eB3,
    const float* __restrict__ eA2, const float* __restrict__ route,
    float* __restrict__ ghs, float* __restrict__ v2)
{
    const int t = blockIdx.x;
    const int tid = threadIdx.x;
    const int wid = tid >> 5, lane = tid & 31;
    const int NI = CK_FFN/256;   // 22
    float ghacc[CK_FFN/256];
    #pragma unroll
    for (int i = 0; i < NI; i++) ghacc[i] = 0.f;
    __shared__ float su1[16], su3[16];
    __shared__ float part[8][16];
    const float* h1r = h1 + (size_t)t*CK_FFN;
    const float* h3r = h3 + (size_t)t*CK_FFN;

    #pragma unroll 1
    for (int e = 0; e < CK_E; e++) {
        float wgt = route[t*CK_E + e];
        if (wgt == 0.f) {
            if (tid < 16) v2[(size_t)t*(CK_E*CK_R) + e*16 + tid] = 0.f;
            continue;
        }
        if (tid < 16) {
            su1[tid] = ua1[((size_t)t*CK_E + e)*16 + tid];
            su3[tid] = ua3[((size_t)t*CK_E + e)*16 + tid];
        }
        __syncthreads();
        float u1[16], u3[16];
        #pragma unroll
        for (int r = 0; r < 16; r++) { u1[r] = su1[r]; u3[r] = su3[r]; }
        float accr[16];
        #pragma unroll
        for (int r = 0; r < 16; r++) accr[r] = 0.f;
        const float* B1 = eB1 + (size_t)e*CK_FFN*16;
        const float* B3 = eB3 + (size_t)e*CK_FFN*16;
        const float* A2 = eA2 + (size_t)e*16*CK_FFN;
        #pragma unroll
        for (int ii = 0; ii < NI; ii++) {
            int f = ii*256 + tid;
            const float4* b1p = (const float4*)(B1 + (size_t)f*16);
            const float4* b3p = (const float4*)(B3 + (size_t)f*16);
            float b1 = 0.f, b3 = 0.f;
            #pragma unroll
            for (int q = 0; q < 4; q++) {
                float4 x1 = b1p[q], x3 = b3p[q];
                b1 += u1[q*4+0]*x1.x + u1[q*4+1]*x1.y + u1[q*4+2]*x1.z + u1[q*4+3]*x1.w;
                b3 += u3[q*4+0]*x3.x + u3[q*4+1]*x3.y + u3[q*4+2]*x3.z + u3[q*4+3]*x3.w;
            }
            float g1 = h1r[f] + CK_LS*b1;
            float g3 = h3r[f] + CK_LS*b3;
            float gh = (g1/(1.f + expf(-g1)))*g3;   // silu(g1)*g3
            ghacc[ii] += wgt*gh;
            #pragma unroll
            for (int r = 0; r < 16; r++) accr[r] += gh * A2[(size_t)r*CK_FFN + f];
        }
        #pragma unroll
        for (int r = 0; r < 16; r++) {
            float v = accr[r];
            #pragma unroll
            for (int o = 16; o; o >>= 1) v += __shfl_down_sync(0xffffffffu, v, o);
            if (lane == 0) part[wid][r] = v;
        }
        __syncthreads();
        if (tid < 16) {
            float s2 = 0.f;
            #pragma unroll
            for (int ww = 0; ww < 8; ww++) s2 += part[ww][tid];
            v2[(size_t)t*(CK_E*CK_R) + e*16 + tid] = wgt*CK_LS*s2;
        }
        __syncthreads();
    }
    float* go = ghs + (size_t)t*CK_FFN;
    #pragma unroll
    for (int ii = 0; ii < NI; ii++) go[ii*256 + tid] = ghacc[ii];
}

// ---------------------------------------------------------------------------
// fpre[t,d] = data2[t,d] + sum_{e,r} v2[t,e*16+r] * eB2[e][d][r]
// ---------------------------------------------------------------------------
__global__ void k_moe_up(const float* __restrict__ d2, const float* __restrict__ v2,
                         const float* __restrict__ eB2, const float* __restrict__ route,
                         float* __restrict__ out) {
    int t = blockIdx.x, tid = threadIdx.x;
    __shared__ float sv[128];
    __shared__ int act[8];
    if (tid < 128) sv[tid] = v2[(size_t)t*128 + tid];
    if (tid < 8)   act[tid] = (route[t*CK_E + tid] != 0.f) ? 1 : 0;
    __syncthreads();
    for (int d = tid; d < CK_D; d += 256) {
        float s = d2[(size_t)t*CK_D + d];
        #pragma unroll 1
        for (int e = 0; e < 8; e++) {
            if (!act[e]) continue;
            const float4* bp = (const float4*)(eB2 + ((size_t)e*CK_D + d)*16);
            #pragma unroll
            for (int q = 0; q < 4; q++) {
                float4 bb = bp[q];
                s += sv[e*16+q*4+0]*bb.x + sv[e*16+q*4+1]*bb.y
                   + sv[e*16+q*4+2]*bb.z + sv[e*16+q*4+3]*bb.w;
            }
        }
        out[(size_t)t*CK_D + d] = s;
    }
}

// ---------------------------------------------------------------------------
// Launch
// ---------------------------------------------------------------------------
extern "C" void kernel_launch(void* const* d_in, const int* in_sizes, int n_in,
                              void* d_out, int out_size) {
    (void)in_sizes; (void)n_in; (void)out_size;
    const float* data  = (const float*)d_in[0];
    const float* rc    = (const float*)d_in[2];
    const float* rs    = (const float*)d_in[3];
    const float* att_w = (const float*)d_in[4];
    const float* ffn_w = (const float*)d_in[5];
    const float* wq    = (const float*)d_in[6];
    const float* wk    = (const float*)d_in[7];
    const float* wv    = (const float*)d_in[8];
    const float* wo    = (const float*)d_in[9];
    const float* lqA   = (const float*)d_in[10];
    const float* lqB   = (const float*)d_in[11];
    const float* lkA   = (const float*)d_in[12];
    const float* lkB   = (const float*)d_in[13];
    const float* lvA   = (const float*)d_in[14];
    const float* lvB   = (const float*)d_in[15];
    const float* loA   = (const float*)d_in[16];
    const float* loB   = (const float*)d_in[17];
    const float* w1    = (const float*)d_in[18];
    const float* w2    = (const float*)d_in[19];
    const float* w3    = (const float*)d_in[20];
    const float* gatew = (const float*)d_in[21];
    const float* eA1   = (const float*)d_in[22];
    const float* eB1   = (const float*)d_in[23];
    const float* eA2   = (const float*)d_in[24];
    const float* eB2   = (const float*)d_in[25];
    const float* eA3   = (const float*)d_in[26];
    const float* eB3   = (const float*)d_in[27];
    float* out = (float*)d_out;

    float *p_h,*p_hn,*p_xq,*p_xk,*p_xv,*p_sc,*p_ao,*p_d2,*p_uq,*p_uk,*p_uv,*p_uo;
    float *p_route,*p_ua1,*p_ua3,*p_h1,*p_h3,*p_ghs,*p_v2,*p_fpre;
    cudaGetSymbolAddress((void**)&p_h,    g_h);
    cudaGetSymbolAddress((void**)&p_hn,   g_hn);
    cudaGetSymbolAddress((void**)&p_xq,   g_xq);
    cudaGetSymbolAddress((void**)&p_xk,   g_xk);
    cudaGetSymbolAddress((void**)&p_xv,   g_xv);
    cudaGetSymbolAddress((void**)&p_sc,   g_sc);
    cudaGetSymbolAddress((void**)&p_ao,   g_ao);
    cudaGetSymbolAddress((void**)&p_d2,   g_d2);
    cudaGetSymbolAddress((void**)&p_uq,   g_uq);
    cudaGetSymbolAddress((void**)&p_uk,   g_uk);
    cudaGetSymbolAddress((void**)&p_uv,   g_uv);
    cudaGetSymbolAddress((void**)&p_uo,   g_uo);
    cudaGetSymbolAddress((void**)&p_route,g_route);
    cudaGetSymbolAddress((void**)&p_ua1,  g_ua1);
    cudaGetSymbolAddress((void**)&p_ua3,  g_ua3);
    cudaGetSymbolAddress((void**)&p_h1,   g_h1);
    cudaGetSymbolAddress((void**)&p_h3,   g_h3);
    cudaGetSymbolAddress((void**)&p_ghs,  g_ghs);
    cudaGetSymbolAddress((void**)&p_v2,   g_v2);
    cudaGetSymbolAddress((void**)&p_fpre, g_fpre);

    // --- attention path ---
    k_rmsnorm<<<CK_T,256>>>(data, att_w, p_h);
    k_lora_down<<<CK_T,256>>>(p_h, lqA, p_uq);
    k_lora_down<<<CK_T,256>>>(p_h, lkA, p_uk);
    k_lora_down<<<CK_T,256>>>(p_h, lvA, p_uv);
    k_hgemm<<<dim3(CK_D/128,  CK_T/128),256>>>(p_h, wq, p_xq, CK_T, CK_D, CK_D, p_uq, lqB, CK_LS, nullptr);
    k_hgemm<<<dim3(512/128,   CK_T/128),256>>>(p_h, wk, p_xk, CK_T, 512,  CK_D, p_uk, lkB, CK_LS, nullptr);
    k_hgemm<<<dim3(512/128,   CK_T/128),256>>>(p_h, wv, p_xv, CK_T, 512,  CK_D, p_uv, lvB, CK_LS, nullptr);
    k_rope<<<(CK_T*CK_H*64 + 255)/256, 256>>>(p_xq, rc, rs, CK_H,  CK_T*CK_H*64);
    k_rope<<<(CK_T*CK_KV*64 + 255)/256,256>>>(p_xk, rc, rs, CK_KV, CK_T*CK_KV*64);
    k_scores<<<dim3(CK_S/64, CK_S/64, CK_B*CK_H),256>>>(p_xq, p_xk, p_sc);
    k_softmax<<<CK_B*CK_H*CK_S,256>>>(p_sc);
    k_av<<<dim3(CK_S/64, 1, CK_B*CK_H),256>>>(p_sc, p_xv, p_ao);
    k_lora_down<<<CK_T,256>>>(p_ao, loA, p_uo);
    k_hgemm<<<dim3(CK_D/128, CK_T/128),256>>>(p_ao, wo, p_d2, CK_T, CK_D, CK_D, p_uo, loB, CK_LS, data);

    // --- MoE path ---
    k_rmsnorm<<<CK_T,256>>>(p_d2, ffn_w, p_hn);
    k_gate<<<CK_T,256>>>(p_hn, gatew, p_route);
    k_expert_down<<<dim3(CK_T, CK_E),256>>>(p_hn, eA1, eA3, p_route, p_ua1, p_ua3);
    k_hgemm<<<dim3(CK_FFN/128, CK_T/128),256>>>(p_hn, w1, p_h1, CK_T, CK_FFN, CK_D, nullptr, nullptr, 0.f, nullptr);
    k_hgemm<<<dim3(CK_FFN/128, CK_T/128),256>>>(p_hn, w3, p_h3, CK_T, CK_FFN, CK_D, nullptr, nullptr, 0.f, nullptr);
    k_moe_expert<<<CK_T,256>>>(p_h1, p_h3, p_ua1, p_ua3, eB1, eB3, eA2, p_route, p_ghs, p_v2);
    k_moe_up<<<CK_T,256>>>(p_d2, p_v2, eB2, p_route, p_fpre);
    k_hgemm<<<dim3(CK_D/128, CK_T/128),256>>>(p_ghs, w2, out, CK_T, CK_D, CK_FFN, nullptr, nullptr, 0.f, p_fpre);
}

// round 7
// speedup vs baseline: 2.0453x; 1.2198x over previous
#include <cuda_runtime.h>
#include <cuda_bf16.h>
#include <math.h>
#include <stdint.h>

#define CK_B   4
#define CK_S   512
#define CK_D   2048
#define CK_H   16
#define CK_KV  4
#define CK_HD  128
#define CK_T   2048          // B*S
#define CK_FFN 5632
#define CK_E   8
#define CK_R   16
#define CK_LS  2.0f          // 32/16

// ---------------------------------------------------------------------------
// fp32 scratch
// ---------------------------------------------------------------------------
__device__ float g_h   [CK_T*CK_D];
__device__ float g_hn  [CK_T*CK_D];
__device__ float g_xq  [CK_T*CK_D];
__device__ float g_xk  [CK_T*CK_KV*CK_HD];
__device__ float g_xv  [CK_T*CK_KV*CK_HD];
__device__ float g_sc  [(size_t)CK_B*CK_H*CK_S*CK_S];
__device__ float g_ao  [CK_T*CK_D];
__device__ float g_d2  [CK_T*CK_D];
__device__ float g_uq  [CK_T*CK_R];
__device__ float g_uk  [CK_T*CK_R];
__device__ float g_uv  [CK_T*CK_R];
__device__ float g_uo  [CK_T*CK_R];
__device__ float g_route[CK_T*CK_E];
__device__ float g_ua1 [CK_T*CK_E*CK_R];
__device__ float g_ua3 [CK_T*CK_E*CK_R];
__device__ float g_h1  [(size_t)CK_T*CK_FFN];
__device__ float g_h3  [(size_t)CK_T*CK_FFN];
__device__ float g_ghs [(size_t)CK_T*CK_FFN];
__device__ float g_v2  [CK_T*CK_E*CK_R];
__device__ float g_fpre[CK_T*CK_D];

// ---------------------------------------------------------------------------
// bf16 hi/lo split scratch (pre-converted operands for tensor-core GEMMs)
// ---------------------------------------------------------------------------
#define NWQ (CK_D*CK_D)
#define NWK (512*CK_D)
#define NW1 (CK_FFN*CK_D)
__device__ __align__(16) __nv_bfloat16 g_wq_h[NWQ],  g_wq_l[NWQ];
__device__ __align__(16) __nv_bfloat16 g_wk_h[NWK],  g_wk_l[NWK];
__device__ __align__(16) __nv_bfloat16 g_wv_h[NWK],  g_wv_l[NWK];
__device__ __align__(16) __nv_bfloat16 g_wo_h[NWQ],  g_wo_l[NWQ];
__device__ __align__(16) __nv_bfloat16 g_w1_h[NW1],  g_w1_l[NW1];
__device__ __align__(16) __nv_bfloat16 g_w3_h[NW1],  g_w3_l[NW1];
__device__ __align__(16) __nv_bfloat16 g_w2_h[NW1],  g_w2_l[NW1];
__device__ __align__(16) __nv_bfloat16 g_xh_h[CK_T*CK_D],  g_xh_l[CK_T*CK_D];     // h
__device__ __align__(16) __nv_bfloat16 g_aoh[CK_T*CK_D],   g_aol[CK_T*CK_D];      // ao
__device__ __align__(16) __nv_bfloat16 g_hnh[CK_T*CK_D],   g_hnl[CK_T*CK_D];      // hn
__device__ __align__(16) __nv_bfloat16 g_gsh[(size_t)CK_T*CK_FFN], g_gsl[(size_t)CK_T*CK_FFN]; // ghs

// ===========================================================================
// helpers
// ===========================================================================
__device__ __forceinline__ uint32_t smem_u32(const void* p) {
    uint32_t a;
    asm("{ .reg .u64 t; cvta.to.shared.u64 t, %1; cvt.u32.u64 %0, t; }" : "=r"(a) : "l"(p));
    return a;
}
#define CP_ASYNC16(dst_u32, src_ptr) \
    asm volatile("cp.async.cg.shared.global [%0], [%1], 16;" :: "r"(dst_u32), "l"(src_ptr))
#define CP_COMMIT() asm volatile("cp.async.commit_group;" ::: "memory")
#define CP_WAIT(n)  asm volatile("cp.async.wait_group %0;" :: "n"(n) : "memory")

__device__ __forceinline__ void mma16816(float* d, const uint32_t* a,
                                         uint32_t b0, uint32_t b1) {
    asm volatile(
        "mma.sync.aligned.m16n8k16.row.col.f32.bf16.bf16.f32 "
        "{%0,%1,%2,%3}, {%4,%5,%6,%7}, {%8,%9}, {%0,%1,%2,%3};"
        : "+f"(d[0]), "+f"(d[1]), "+f"(d[2]), "+f"(d[3])
        : "r"(a[0]), "r"(a[1]), "r"(a[2]), "r"(a[3]), "r"(b0), "r"(b1));
}

__device__ __forceinline__ void split4(__nv_bfloat16* hp, __nv_bfloat16* lp, float4 v) {
    float vs[4] = {v.x, v.y, v.z, v.w};
    __nv_bfloat16 h[4], l[4];
    #pragma unroll
    for (int i = 0; i < 4; i++) {
        h[i] = __float2bfloat16(vs[i]);
        l[i] = __float2bfloat16(vs[i] - __bfloat162float(h[i]));
    }
    *(__nv_bfloat162*)(hp + 0) = __halves2bfloat162(h[0], h[1]);
    *(__nv_bfloat162*)(hp + 2) = __halves2bfloat162(h[2], h[3]);
    *(__nv_bfloat162*)(lp + 0) = __halves2bfloat162(l[0], l[1]);
    *(__nv_bfloat162*)(lp + 2) = __halves2bfloat162(l[2], l[3]);
}

// ---------------------------------------------------------------------------
// k_split: fp32 -> (hi bf16, lo bf16), 4 elems/thread
// ---------------------------------------------------------------------------
__global__ void k_split(const float* __restrict__ x, __nv_bfloat16* __restrict__ h,
                        __nv_bfloat16* __restrict__ l, int n) {
    int i = (blockIdx.x*256 + threadIdx.x)*4;
    if (i >= n) return;
    float4 v = *(const float4*)(x + i);
    split4(h + i, l + i, v);
}

// ===========================================================================
// k_hgemm2: tensor-core split-bf16 GEMM with cp.async double buffering
//   C = A @ W^T [+ lscale*U@V^T] [+ res],  A,W pre-split into hi/lo bf16.
//   Tiles 128x128x32, 256 threads (8 warps 4x2), warp tile 32x64.
// ===========================================================================
#define HG_LD   40
#define HG_TILE (128*HG_LD)        // elems per (comp,buf) tile
#define HG_TILEB (HG_TILE*2)       // bytes
#define HG_SMEM (8*HG_TILEB)       // 81920 bytes

__global__ void __launch_bounds__(256, 2) k_hgemm2(
    const __nv_bfloat16* __restrict__ Ah, const __nv_bfloat16* __restrict__ Al,
    const __nv_bfloat16* __restrict__ Wh, const __nv_bfloat16* __restrict__ Wl,
    float* __restrict__ C, int M, int N, int K,
    const float* __restrict__ U, const float* __restrict__ V, float lscale,
    const float* __restrict__ res)
{
    extern __shared__ __align__(16) __nv_bfloat16 sm[];
    __nv_bfloat16* pAh = sm;
    __nv_bfloat16* pAl = sm + 2*HG_TILE;
    __nv_bfloat16* pWh = sm + 4*HG_TILE;
    __nv_bfloat16* pWl = sm + 6*HG_TILE;
    const uint32_t sb   = smem_u32(sm);
    const uint32_t sbAh = sb;
    const uint32_t sbAl = sb + 2*HG_TILEB;
    const uint32_t sbWh = sb + 4*HG_TILEB;
    const uint32_t sbWl = sb + 6*HG_TILEB;

    const int tid  = threadIdx.x;
    const int wid  = tid >> 5, lane = tid & 31;
    const int g    = lane >> 2, tg = lane & 3;
    const int warpM = wid & 3;
    const int warpN = wid >> 2;
    const int bm = blockIdx.y * 128;
    const int bn = blockIdx.x * 128;

    float acc[2][8][4];
    #pragma unroll
    for (int mi = 0; mi < 2; mi++)
        #pragma unroll
        for (int ni = 0; ni < 8; ni++)
            #pragma unroll
            for (int q = 0; q < 4; q++) acc[mi][ni][q] = 0.f;

    const int NC = K / 32;
    const int total = NC + (U ? 1 : 0);

    // async load of a regular K-chunk into buffer `buf`
    auto load_async = [&](int c, int buf) {
        const int k0 = c * 32;
        const uint32_t bo = (uint32_t)buf * HG_TILEB;
        #pragma unroll
        for (int it = 0; it < 2; it++) {
            int id = it*256 + tid;
            int r = id >> 2, sg = (id & 3) * 8;
            uint32_t so = bo + (uint32_t)(r*HG_LD + sg)*2;
            size_t ga = (size_t)(bm + r)*K + k0 + sg;
            size_t gw = (size_t)(bn + r)*K + k0 + sg;
            CP_ASYNC16(sbAh + so, Ah + ga);
            CP_ASYNC16(sbAl + so, Al + ga);
            CP_ASYNC16(sbWh + so, Wh + gw);
            CP_ASYNC16(sbWl + so, Wl + gw);
        }
        CP_COMMIT();
    };

    // manual load of the rank-16 LoRA tail chunk (fp32 -> hi/lo in-kernel)
    auto load_lora = [&](int buf) {
        __nv_bfloat16* dAh = pAh + buf*HG_TILE;
        __nv_bfloat16* dAl = pAl + buf*HG_TILE;
        __nv_bfloat16* dWh = pWh + buf*HG_TILE;
        __nv_bfloat16* dWl = pWl + buf*HG_TILE;
        #pragma unroll
        for (int l = 0; l < 4; l++) {
            int id = l*256 + tid;
            int r = id >> 3, c4 = (id & 7)*4;
            float4 va = make_float4(0.f,0.f,0.f,0.f);
            float4 vw = make_float4(0.f,0.f,0.f,0.f);
            if (c4 < 16) {
                va = *(const float4*)(U + (size_t)(bm + r)*16 + c4);
                va.x *= lscale; va.y *= lscale; va.z *= lscale; va.w *= lscale;
                vw = *(const float4*)(V + (size_t)(bn + r)*16 + c4);
            }
            split4(dAh + r*HG_LD + c4, dAl + r*HG_LD + c4, va);
            split4(dWh + r*HG_LD + c4, dWl + r*HG_LD + c4, vw);
        }
    };

    load_async(0, 0);

    for (int c = 0; c < total; c++) {
        const int cur = c & 1, nb = (c + 1) & 1;
        const bool have_next = (c + 1 < total);
        const bool next_async = (c + 1 < NC);
        if (have_next) {
            if (next_async) load_async(c + 1, nb);
            else            load_lora(nb);
        }
        if (c < NC) {
            if (have_next && next_async) { CP_WAIT(1); }
            else                         { CP_WAIT(0); }
        }
        __syncthreads();

        const __nv_bfloat16* bAh = pAh + cur*HG_TILE;
        const __nv_bfloat16* bAl = pAl + cur*HG_TILE;
        const __nv_bfloat16* bWh = pWh + cur*HG_TILE;
        const __nv_bfloat16* bWl = pWl + cur*HG_TILE;

        #pragma unroll
        for (int ks = 0; ks < 2; ks++) {
            const int col0 = ks*16 + tg*2;
            uint32_t ah[2][4], al[2][4];
            #pragma unroll
            for (int mi = 0; mi < 2; mi++) {
                int r0 = warpM*32 + mi*16 + g;
                ah[mi][0] = *(const uint32_t*)(bAh + r0*HG_LD + col0);
                ah[mi][1] = *(const uint32_t*)(bAh + (r0+8)*HG_LD + col0);
                ah[mi][2] = *(const uint32_t*)(bAh + r0*HG_LD + col0 + 8);
                ah[mi][3] = *(const uint32_t*)(bAh + (r0+8)*HG_LD + col0 + 8);
                al[mi][0] = *(const uint32_t*)(bAl + r0*HG_LD + col0);
                al[mi][1] = *(const uint32_t*)(bAl + (r0+8)*HG_LD + col0);
                al[mi][2] = *(const uint32_t*)(bAl + r0*HG_LD + col0 + 8);
                al[mi][3] = *(const uint32_t*)(bAl + (r0+8)*HG_LD + col0 + 8);
            }
            #pragma unroll
            for (int ni = 0; ni < 8; ni++) {
                int rn = warpN*64 + ni*8 + g;
                uint32_t bh0 = *(const uint32_t*)(bWh + rn*HG_LD + col0);
                uint32_t bh1 = *(const uint32_t*)(bWh + rn*HG_LD + col0 + 8);
                uint32_t bl0 = *(const uint32_t*)(bWl + rn*HG_LD + col0);
                uint32_t bl1 = *(const uint32_t*)(bWl + rn*HG_LD + col0 + 8);
                #pragma unroll
                for (int mi = 0; mi < 2; mi++) {
                    mma16816(acc[mi][ni], ah[mi], bh0, bh1);
                    mma16816(acc[mi][ni], ah[mi], bl0, bl1);
                    mma16816(acc[mi][ni], al[mi], bh0, bh1);
                }
            }
        }
        __syncthreads();
    }

    #pragma unroll
    for (int mi = 0; mi < 2; mi++) {
        size_t r0 = (size_t)(bm + warpM*32 + mi*16 + g);
        #pragma unroll
        for (int ni = 0; ni < 8; ni++) {
            size_t c0 = (size_t)(bn + warpN*64 + ni*8 + tg*2);
            float2 o0 = make_float2(acc[mi][ni][0], acc[mi][ni][1]);
            float2 o1 = make_float2(acc[mi][ni][2], acc[mi][ni][3]);
            if (res) {
                float2 r0v = *(const float2*)(res + r0*N + c0);
                float2 r1v = *(const float2*)(res + (r0+8)*N + c0);
                o0.x += r0v.x; o0.y += r0v.y;
                o1.x += r1v.x; o1.y += r1v.y;
            }
            *(float2*)(C + r0*N + c0)     = o0;
            *(float2*)(C + (r0+8)*N + c0) = o1;
        }
    }
}

// ---------------------------------------------------------------------------
// RMSNorm
// ---------------------------------------------------------------------------
__global__ void k_rmsnorm(const float* __restrict__ x, const float* __restrict__ w,
                          float* __restrict__ o) {
    int t = blockIdx.x;
    const float* xr = x + (size_t)t*CK_D;
    float ss = 0.f;
    for (int i = threadIdx.x; i < CK_D; i += 256) { float v = xr[i]; ss += v*v; }
    __shared__ float red[256];
    red[threadIdx.x] = ss; __syncthreads();
    for (int s = 128; s > 0; s >>= 1) {
        if (threadIdx.x < s) red[threadIdx.x] += red[threadIdx.x+s];
        __syncthreads();
    }
    float sc = rsqrtf(red[0]/(float)CK_D + 1e-5f);
    float* orow = o + (size_t)t*CK_D;
    for (int i = threadIdx.x; i < CK_D; i += 256) orow[i] = xr[i]*sc*w[i];
}

// ---------------------------------------------------------------------------
// LoRA down-projection
// ---------------------------------------------------------------------------
__global__ void k_lora_down(const float* __restrict__ X, const float* __restrict__ A,
                            float* __restrict__ U) {
    int t = blockIdx.x;
    __shared__ float sx[CK_D];
    for (int i = threadIdx.x; i < CK_D; i += 256) sx[i] = X[(size_t)t*CK_D + i];
    __syncthreads();
    int w = threadIdx.x >> 5, lane = threadIdx.x & 31;
    for (int r = w; r < CK_R; r += 8) {
        const float* ar = A + (size_t)r*CK_D;
        float p = 0.f;
        for (int d = lane; d < CK_D; d += 32) p += sx[d]*ar[d];
        for (int o = 16; o; o >>= 1) p += __shfl_down_sync(0xffffffffu, p, o);
        if (lane == 0) U[t*CK_R + r] = p;
    }
}

// ---------------------------------------------------------------------------
// RoPE (in place)
// ---------------------------------------------------------------------------
__global__ void k_rope(float* __restrict__ x, const float* __restrict__ cs,
                       const float* __restrict__ sn, int nh, int total) {
    int i = blockIdx.x*256 + threadIdx.x;
    if (i >= total) return;
    int d2 = i & 63;
    int h  = (i >> 6) % nh;
    int t  = i / (64*nh);
    int s  = t & (CK_S - 1);
    float c  = cs[s*64 + d2];
    float si = sn[s*64 + d2];
    float* p = x + ((size_t)t*nh + h)*CK_HD + 2*d2;
    float x1 = p[0], x2 = p[1];
    p[0] = x1*c - x2*si;
    p[1] = x1*si + x2*c;
}

// ---------------------------------------------------------------------------
// scores (upper-triangle tiles skipped)
// ---------------------------------------------------------------------------
__global__ void __launch_bounds__(256) k_scores(const float* __restrict__ xq,
                                                const float* __restrict__ xk,
                                                float* __restrict__ sc) {
    const int t0 = blockIdx.x*64, s0 = blockIdx.y*64;
    if (t0 > s0 + 63) return;
    const int bh = blockIdx.z, b = bh >> 4, h = bh & 15, kv = h >> 2;
    const float* Q  = xq + ((size_t)b*CK_S*CK_H  + h )*CK_HD;
    const float* Kp = xk + ((size_t)b*CK_S*CK_KV + kv)*CK_HD;
    __shared__ float Qs[16][64], Ks[16][64];
    const int tid = threadIdx.x;
    const int lrow = tid >> 2, lk = (tid & 3)*4;
    const int ty = tid >> 4, tx = tid & 15;
    float acc[4][4];
    #pragma unroll
    for (int i=0;i<4;i++)
        #pragma unroll
        for (int j=0;j<4;j++) acc[i][j]=0.f;

    for (int k0 = 0; k0 < CK_HD; k0 += 16) {
        float4 q4 = *(const float4*)(Q  + (size_t)(s0+lrow)*(CK_H*CK_HD)  + k0 + lk);
        Qs[lk+0][lrow]=q4.x; Qs[lk+1][lrow]=q4.y; Qs[lk+2][lrow]=q4.z; Qs[lk+3][lrow]=q4.w;
        float4 k4 = *(const float4*)(Kp + (size_t)(t0+lrow)*(CK_KV*CK_HD) + k0 + lk);
        Ks[lk+0][lrow]=k4.x; Ks[lk+1][lrow]=k4.y; Ks[lk+2][lrow]=k4.z; Ks[lk+3][lrow]=k4.w;
        __syncthreads();
        #pragma unroll
        for (int k = 0; k < 16; k++) {
            float4 a  = *(const float4*)&Qs[k][ty*4];
            float4 bb = *(const float4*)&Ks[k][tx*4];
            float ra[4] = {a.x,a.y,a.z,a.w};
            float rb[4] = {bb.x,bb.y,bb.z,bb.w};
            #pragma unroll
            for (int i=0;i<4;i++)
                #pragma unroll
                for (int j=0;j<4;j++) acc[i][j] += ra[i]*rb[j];
        }
        __syncthreads();
    }
    const float scl = 0.08838834764831845f;
    float* out = sc + (size_t)bh*CK_S*CK_S;
    #pragma unroll
    for (int i = 0; i < 4; i++) {
        size_t srow = (size_t)(s0 + ty*4 + i);
        float4 o;
        o.x=acc[i][0]*scl; o.y=acc[i][1]*scl; o.z=acc[i][2]*scl; o.w=acc[i][3]*scl;
        *(float4*)(out + srow*CK_S + t0 + tx*4) = o;
    }
}

// ---------------------------------------------------------------------------
// Causal softmax, single pass (row=512, 2 elems/thread in registers)
// ---------------------------------------------------------------------------
__global__ void k_softmax(float* __restrict__ sc) {
    int row = blockIdx.x;            // bh*512 + s
    int s = row & (CK_S - 1);
    float* p = sc + (size_t)row*CK_S;
    int L = s + 1;
    int tid = threadIdx.x;
    float v0 = (tid       < L) ? p[tid]       : -1e30f;
    float v1 = (tid + 256 < L) ? p[tid + 256] : -1e30f;
    __shared__ float red[256];
    red[tid] = fmaxf(v0, v1); __syncthreads();
    for (int st = 128; st; st >>= 1) {
        if (tid < st) red[tid] = fmaxf(red[tid], red[tid+st]);
        __syncthreads();
    }
    float m = red[0]; __syncthreads();
    float e0 = (tid       < L) ? expf(v0 - m) : 0.f;
    float e1 = (tid + 256 < L) ? expf(v1 - m) : 0.f;
    red[tid] = e0 + e1; __syncthreads();
    for (int st = 128; st; st >>= 1) {
        if (tid < st) red[tid] += red[tid+st];
        __syncthreads();
    }
    float inv = 1.f / red[0];
    p[tid]       = e0 * inv;
    p[tid + 256] = e1 * inv;
}

// ---------------------------------------------------------------------------
// out = attn @ V
// ---------------------------------------------------------------------------
__global__ void __launch_bounds__(256) k_av(const float* __restrict__ attn,
                                            const float* __restrict__ xv,
                                            float* __restrict__ out) {
    const int s0 = blockIdx.x*64;
    const int bh = blockIdx.z, b = bh >> 4, h = bh & 15, kv = h >> 2;
    const float* Ab = attn + (size_t)bh*CK_S*CK_S;
    const float* Vb = xv + ((size_t)b*CK_S*CK_KV + kv)*CK_HD;
    __shared__ float As[64][33];
    __shared__ float Vs[32][128];
    const int tid = threadIdx.x;
    const int ty = tid >> 5, tx = tid & 31;
    float acc[8][4];
    #pragma unroll
    for (int i=0;i<8;i++)
        #pragma unroll
        for (int j=0;j<4;j++) acc[i][j]=0.f;

    for (int k0 = 0; k0 < CK_S; k0 += 32) {
        #pragma unroll
        for (int l = 0; l < 2; l++) {
            int id = tid + l*256, r = id >> 3, c4 = (id & 7)*4;
            float4 a = *(const float4*)(Ab + (size_t)(s0+r)*CK_S + k0 + c4);
            As[r][c4]=a.x; As[r][c4+1]=a.y; As[r][c4+2]=a.z; As[r][c4+3]=a.w;
        }
        #pragma unroll
        for (int l = 0; l < 4; l++) {
            int id = tid + l*256, r = id >> 5, c4 = (id & 31)*4;
            float4 v = *(const float4*)(Vb + (size_t)(k0+r)*(CK_KV*CK_HD) + c4);
            *(float4*)&Vs[r][c4] = v;
        }
        __syncthreads();
        #pragma unroll
        for (int k = 0; k < 32; k++) {
            float4 vv = *(const float4*)&Vs[k][tx*4];
            #pragma unroll
            for (int i = 0; i < 8; i++) {
                float a = As[ty*8+i][k];
                acc[i][0]+=a*vv.x; acc[i][1]+=a*vv.y; acc[i][2]+=a*vv.z; acc[i][3]+=a*vv.w;
            }
        }
        __syncthreads();
    }
    #pragma unroll
    for (int i = 0; i < 8; i++) {
        int s = s0 + ty*8 + i;
        float4 o; o.x=acc[i][0]; o.y=acc[i][1]; o.z=acc[i][2]; o.w=acc[i][3];
        *(float4*)(out + ((size_t)(b*CK_S+s)*CK_H + h)*CK_HD + tx*4) = o;
    }
}

// ---------------------------------------------------------------------------
// Gate
// ---------------------------------------------------------------------------
__global__ void k_gate(const float* __restrict__ hn, const float* __restrict__ gw,
                       float* __restrict__ route) {
    int t = blockIdx.x;
    __shared__ float sl[8];
    int w = threadIdx.x >> 5, lane = threadIdx.x & 31;
    const float* xr = hn + (size_t)t*CK_D;
    const float* gr = gw + (size_t)w*CK_D;
    float p = 0.f;
    for (int d = lane; d < CK_D; d += 32) p += xr[d]*gr[d];
    for (int o = 16; o; o >>= 1) p += __shfl_down_sync(0xffffffffu, p, o);
    if (lane == 0) sl[w] = p;
    __syncthreads();
    if (threadIdx.x == 0) {
        int i0 = 0;
        for (int e = 1; e < 8; e++) if (sl[e] > sl[i0]) i0 = e;
        int i1 = -1;
        for (int e = 0; e < 8; e++) { if (e == i0) continue; if (i1 < 0 || sl[e] > sl[i1]) i1 = e; }
        float m = sl[i0];
        float v0 = expf(sl[i0]-m), v1 = expf(sl[i1]-m);
        float inv = 1.f/(v0+v1);
        float* rr = route + (size_t)t*CK_E;
        #pragma unroll
        for (int e = 0; e < 8; e++) rr[e] = 0.f;
        rr[i0] = v0*inv; rr[i1] = v1*inv;
    }
}

// ---------------------------------------------------------------------------
// Expert LoRA downs
// ---------------------------------------------------------------------------
__global__ void k_expert_down(const float* __restrict__ X, const float* __restrict__ A1,
                              const float* __restrict__ A3, const float* __restrict__ route,
                              float* __restrict__ U1, float* __restrict__ U3) {
    int t = blockIdx.x, e = blockIdx.y;
    if (route[t*CK_E + e] == 0.f) return;
    __shared__ float sx[CK_D];
    for (int i = threadIdx.x; i < CK_D; i += 256) sx[i] = X[(size_t)t*CK_D + i];
    __syncthreads();
    int w = threadIdx.x >> 5, lane = threadIdx.x & 31;
    const float* a1 = A1 + (size_t)e*CK_R*CK_D;
    const float* a3 = A3 + (size_t)e*CK_R*CK_D;
    for (int r = w; r < CK_R; r += 8) {
        float p1 = 0.f, p3 = 0.f;
        for (int d = lane; d < CK_D; d += 32) {
            float xv = sx[d];
            p1 += xv*a1[(size_t)r*CK_D + d];
            p3 += xv*a3[(size_t)r*CK_D + d];
        }
        for (int o = 16; o; o >>= 1) {
            p1 += __shfl_down_sync(0xffffffffu, p1, o);
            p3 += __shfl_down_sync(0xffffffffu, p3, o);
        }
        if (lane == 0) {
            U1[((size_t)t*CK_E + e)*CK_R + r] = p1;
            U3[((size_t)t*CK_E + e)*CK_R + r] = p3;
        }
    }
}

// ---------------------------------------------------------------------------
// Fused per-token MoE combine
// ---------------------------------------------------------------------------
__global__ void __launch_bounds__(256) k_moe_expert(
    const float* __restrict__ h1, const float* __restrict__ h3,
    const float* __restrict__ ua1, const float* __restrict__ ua3,
    const float* __restrict__ eB1, const float* __restrict__ eB3,
    const float* __restrict__ eA2, const float* __restrict__ route,
    float* __restrict__ ghs, float* __restrict__ v2)
{
    const int t = blockIdx.x;
    const int tid = threadIdx.x;
    const int wid = tid >> 5, lane = tid & 31;
    const int NI = CK_FFN/256;   // 22
    float ghacc[CK_FFN/256];
    #pragma unroll
    for (int i = 0; i < NI; i++) ghacc[i] = 0.f;
    __shared__ float su1[16], su3[16];
    __shared__ float part[8][16];
    const float* h1r = h1 + (size_t)t*CK_FFN;
    const float* h3r = h3 + (size_t)t*CK_FFN;

    #pragma unroll 1
    for (int e = 0; e < CK_E; e++) {
        float wgt = route[t*CK_E + e];
        if (wgt == 0.f) {
            if (tid < 16) v2[(size_t)t*(CK_E*CK_R) + e*16 + tid] = 0.f;
            continue;
        }
        if (tid < 16) {
            su1[tid] = ua1[((size_t)t*CK_E + e)*16 + tid];
            su3[tid] = ua3[((size_t)t*CK_E + e)*16 + tid];
        }
        __syncthreads();
        float u1[16], u3[16];
        #pragma unroll
        for (int r = 0; r < 16; r++) { u1[r] = su1[r]; u3[r] = su3[r]; }
        float accr[16];
        #pragma unroll
        for (int r = 0; r < 16; r++) accr[r] = 0.f;
        const float* B1 = eB1 + (size_t)e*CK_FFN*16;
        const float* B3 = eB3 + (size_t)e*CK_FFN*16;
        const float* A2 = eA2 + (size_t)e*16*CK_FFN;
        #pragma unroll
        for (int ii = 0; ii < NI; ii++) {
            int f = ii*256 + tid;
            const float4* b1p = (const float4*)(B1 + (size_t)f*16);
            const float4* b3p = (const float4*)(B3 + (size_t)f*16);
            float b1 = 0.f, b3 = 0.f;
            #pragma unroll
            for (int q = 0; q < 4; q++) {
                float4 x1 = b1p[q], x3 = b3p[q];
                b1 += u1[q*4+0]*x1.x + u1[q*4+1]*x1.y + u1[q*4+2]*x1.z + u1[q*4+3]*x1.w;
                b3 += u3[q*4+0]*x3.x + u3[q*4+1]*x3.y + u3[q*4+2]*x3.z + u3[q*4+3]*x3.w;
            }
            float g1 = h1r[f] + CK_LS*b1;
            float g3 = h3r[f] + CK_LS*b3;
            float gh = (g1/(1.f + expf(-g1)))*g3;
            ghacc[ii] += wgt*gh;
            #pragma unroll
            for (int r = 0; r < 16; r++) accr[r] += gh * A2[(size_t)r*CK_FFN + f];
        }
        #pragma unroll
        for (int r = 0; r < 16; r++) {
            float v = accr[r];
            #pragma unroll
            for (int o = 16; o; o >>= 1) v += __shfl_down_sync(0xffffffffu, v, o);
            if (lane == 0) part[wid][r] = v;
        }
        __syncthreads();
        if (tid < 16) {
            float s2 = 0.f;
            #pragma unroll
            for (int ww = 0; ww < 8; ww++) s2 += part[ww][tid];
            v2[(size_t)t*(CK_E*CK_R) + e*16 + tid] = wgt*CK_LS*s2;
        }
        __syncthreads();
    }
    float* go = ghs + (size_t)t*CK_FFN;
    #pragma unroll
    for (int ii = 0; ii < NI; ii++) go[ii*256 + tid] = ghacc[ii];
}

// ---------------------------------------------------------------------------
// fpre = data2 + v2 @ eB2^T
// ---------------------------------------------------------------------------
__global__ void k_moe_up(const float* __restrict__ d2, const float* __restrict__ v2,
                         const float* __restrict__ eB2, const float* __restrict__ route,
                         float* __restrict__ out) {
    int t = blockIdx.x, tid = threadIdx.x;
    __shared__ float sv[128];
    __shared__ int act[8];
    if (tid < 128) sv[tid] = v2[(size_t)t*128 + tid];
    if (tid < 8)   act[tid] = (route[t*CK_E + tid] != 0.f) ? 1 : 0;
    __syncthreads();
    for (int d = tid; d < CK_D; d += 256) {
        float s = d2[(size_t)t*CK_D + d];
        #pragma unroll 1
        for (int e = 0; e < 8; e++) {
            if (!act[e]) continue;
            const float4* bp = (const float4*)(eB2 + ((size_t)e*CK_D + d)*16);
            #pragma unroll
            for (int q = 0; q < 4; q++) {
                float4 bb = bp[q];
                s += sv[e*16+q*4+0]*bb.x + sv[e*16+q*4+1]*bb.y
                   + sv[e*16+q*4+2]*bb.z + sv[e*16+q*4+3]*bb.w;
            }
        }
        out[(size_t)t*CK_D + d] = s;
    }
}

// ---------------------------------------------------------------------------
// Launch
// ---------------------------------------------------------------------------
extern "C" void kernel_launch(void* const* d_in, const int* in_sizes, int n_in,
                              void* d_out, int out_size) {
    (void)in_sizes; (void)n_in; (void)out_size;
    const float* data  = (const float*)d_in[0];
    const float* rc    = (const float*)d_in[2];
    const float* rs    = (const float*)d_in[3];
    const float* att_w = (const float*)d_in[4];
    const float* ffn_w = (const float*)d_in[5];
    const float* wq    = (const float*)d_in[6];
    const float* wk    = (const float*)d_in[7];
    const float* wv    = (const float*)d_in[8];
    const float* wo    = (const float*)d_in[9];
    const float* lqA   = (const float*)d_in[10];
    const float* lqB   = (const float*)d_in[11];
    const float* lkA   = (const float*)d_in[12];
    const float* lkB   = (const float*)d_in[13];
    const float* lvA   = (const float*)d_in[14];
    const float* lvB   = (const float*)d_in[15];
    const float* loA   = (const float*)d_in[16];
    const float* loB   = (const float*)d_in[17];
    const float* w1    = (const float*)d_in[18];
    const float* w2    = (const float*)d_in[19];
    const float* w3    = (const float*)d_in[20];
    const float* gatew = (const float*)d_in[21];
    const float* eA1   = (const float*)d_in[22];
    const float* eB1   = (const float*)d_in[23];
    const float* eA2   = (const float*)d_in[24];
    const float* eB2   = (const float*)d_in[25];
    const float* eA3   = (const float*)d_in[26];
    const float* eB3   = (const float*)d_in[27];
    float* out = (float*)d_out;

    float *p_h,*p_hn,*p_xq,*p_xk,*p_xv,*p_sc,*p_ao,*p_d2,*p_uq,*p_uk,*p_uv,*p_uo;
    float *p_route,*p_ua1,*p_ua3,*p_h1,*p_h3,*p_ghs,*p_v2,*p_fpre;
    cudaGetSymbolAddress((void**)&p_h,    g_h);
    cudaGetSymbolAddress((void**)&p_hn,   g_hn);
    cudaGetSymbolAddress((void**)&p_xq,   g_xq);
    cudaGetSymbolAddress((void**)&p_xk,   g_xk);
    cudaGetSymbolAddress((void**)&p_xv,   g_xv);
    cudaGetSymbolAddress((void**)&p_sc,   g_sc);
    cudaGetSymbolAddress((void**)&p_ao,   g_ao);
    cudaGetSymbolAddress((void**)&p_d2,   g_d2);
    cudaGetSymbolAddress((void**)&p_uq,   g_uq);
    cudaGetSymbolAddress((void**)&p_uk,   g_uk);
    cudaGetSymbolAddress((void**)&p_uv,   g_uv);
    cudaGetSymbolAddress((void**)&p_uo,   g_uo);
    cudaGetSymbolAddress((void**)&p_route,g_route);
    cudaGetSymbolAddress((void**)&p_ua1,  g_ua1);
    cudaGetSymbolAddress((void**)&p_ua3,  g_ua3);
    cudaGetSymbolAddress((void**)&p_h1,   g_h1);
    cudaGetSymbolAddress((void**)&p_h3,   g_h3);
    cudaGetSymbolAddress((void**)&p_ghs,  g_ghs);
    cudaGetSymbolAddress((void**)&p_v2,   g_v2);
    cudaGetSymbolAddress((void**)&p_fpre, g_fpre);

    __nv_bfloat16 *wq_h,*wq_l,*wk_h,*wk_l,*wv_h,*wv_l,*wo_h,*wo_l;
    __nv_bfloat16 *w1_h,*w1_l,*w3_h,*w3_l,*w2_h,*w2_l;
    __nv_bfloat16 *xh_h,*xh_l,*ao_h,*ao_l,*hn_h,*hn_l,*gs_h,*gs_l;
    cudaGetSymbolAddress((void**)&wq_h, g_wq_h); cudaGetSymbolAddress((void**)&wq_l, g_wq_l);
    cudaGetSymbolAddress((void**)&wk_h, g_wk_h); cudaGetSymbolAddress((void**)&wk_l, g_wk_l);
    cudaGetSymbolAddress((void**)&wv_h, g_wv_h); cudaGetSymbolAddress((void**)&wv_l, g_wv_l);
    cudaGetSymbolAddress((void**)&wo_h, g_wo_h); cudaGetSymbolAddress((void**)&wo_l, g_wo_l);
    cudaGetSymbolAddress((void**)&w1_h, g_w1_h); cudaGetSymbolAddress((void**)&w1_l, g_w1_l);
    cudaGetSymbolAddress((void**)&w3_h, g_w3_h); cudaGetSymbolAddress((void**)&w3_l, g_w3_l);
    cudaGetSymbolAddress((void**)&w2_h, g_w2_h); cudaGetSymbolAddress((void**)&w2_l, g_w2_l);
    cudaGetSymbolAddress((void**)&xh_h, g_xh_h); cudaGetSymbolAddress((void**)&xh_l, g_xh_l);
    cudaGetSymbolAddress((void**)&ao_h, g_aoh);  cudaGetSymbolAddress((void**)&ao_l, g_aol);
    cudaGetSymbolAddress((void**)&hn_h, g_hnh);  cudaGetSymbolAddress((void**)&hn_l, g_hnl);
    cudaGetSymbolAddress((void**)&gs_h, g_gsh);  cudaGetSymbolAddress((void**)&gs_l, g_gsl);

    cudaFuncSetAttribute(k_hgemm2, cudaFuncAttributeMaxDynamicSharedMemorySize, HG_SMEM);

    // --- weight splits (graph nodes each call; ~60us total) ---
    k_split<<<NWQ/1024,256>>>(wq, wq_h, wq_l, NWQ);
    k_split<<<NWK/1024,256>>>(wk, wk_h, wk_l, NWK);
    k_split<<<NWK/1024,256>>>(wv, wv_h, wv_l, NWK);
    k_split<<<NWQ/1024,256>>>(wo, wo_h, wo_l, NWQ);
    k_split<<<NW1/1024,256>>>(w1, w1_h, w1_l, NW1);
    k_split<<<NW1/1024,256>>>(w3, w3_h, w3_l, NW1);
    k_split<<<NW1/1024,256>>>(w2, w2_h, w2_l, NW1);

    // --- attention path ---
    k_rmsnorm<<<CK_T,256>>>(data, att_w, p_h);
    k_split<<<(CK_T*CK_D)/1024,256>>>(p_h, xh_h, xh_l, CK_T*CK_D);
    k_lora_down<<<CK_T,256>>>(p_h, lqA, p_uq);
    k_lora_down<<<CK_T,256>>>(p_h, lkA, p_uk);
    k_lora_down<<<CK_T,256>>>(p_h, lvA, p_uv);
    k_hgemm2<<<dim3(CK_D/128, CK_T/128),256,HG_SMEM>>>(xh_h, xh_l, wq_h, wq_l, p_xq, CK_T, CK_D, CK_D, p_uq, lqB, CK_LS, nullptr);
    k_hgemm2<<<dim3(512/128,  CK_T/128),256,HG_SMEM>>>(xh_h, xh_l, wk_h, wk_l, p_xk, CK_T, 512,  CK_D, p_uk, lkB, CK_LS, nullptr);
    k_hgemm2<<<dim3(512/128,  CK_T/128),256,HG_SMEM>>>(xh_h, xh_l, wv_h, wv_l, p_xv, CK_T, 512,  CK_D, p_uv, lvB, CK_LS, nullptr);
    k_rope<<<(CK_T*CK_H*64 + 255)/256, 256>>>(p_xq, rc, rs, CK_H,  CK_T*CK_H*64);
    k_rope<<<(CK_T*CK_KV*64 + 255)/256,256>>>(p_xk, rc, rs, CK_KV, CK_T*CK_KV*64);
    k_scores<<<dim3(CK_S/64, CK_S/64, CK_B*CK_H),256>>>(p_xq, p_xk, p_sc);
    k_softmax<<<CK_B*CK_H*CK_S,256>>>(p_sc);
    k_av<<<dim3(CK_S/64, 1, CK_B*CK_H),256>>>(p_sc, p_xv, p_ao);
    k_split<<<(CK_T*CK_D)/1024,256>>>(p_ao, ao_h, ao_l, CK_T*CK_D);
    k_lora_down<<<CK_T,256>>>(p_ao, loA, p_uo);
    k_hgemm2<<<dim3(CK_D/128, CK_T/128),256,HG_SMEM>>>(ao_h, ao_l, wo_h, wo_l, p_d2, CK_T, CK_D, CK_D, p_uo, loB, CK_LS, data);

    // --- MoE path ---
    k_rmsnorm<<<CK_T,256>>>(p_d2, ffn_w, p_hn);
    k_split<<<(CK_T*CK_D)/1024,256>>>(p_hn, hn_h, hn_l, CK_T*CK_D);
    k_gate<<<CK_T,256>>>(p_hn, gatew, p_route);
    k_expert_down<<<dim3(CK_T, CK_E),256>>>(p_hn, eA1, eA3, p_route, p_ua1, p_ua3);
    k_hgemm2<<<dim3(CK_FFN/128, CK_T/128),256,HG_SMEM>>>(hn_h, hn_l, w1_h, w1_l, p_h1, CK_T, CK_FFN, CK_D, nullptr, nullptr, 0.f, nullptr);
    k_hgemm2<<<dim3(CK_FFN/128, CK_T/128),256,HG_SMEM>>>(hn_h, hn_l, w3_h, w3_l, p_h3, CK_T, CK_FFN, CK_D, nullptr, nullptr, 0.f, nullptr);
    k_moe_expert<<<CK_T,256>>>(p_h1, p_h3, p_ua1, p_ua3, eB1, eB3, eA2, p_route, p_ghs, p_v2);
    k_split<<<(int)(((size_t)CK_T*CK_FFN)/1024),256>>>(p_ghs, gs_h, gs_l, CK_T*CK_FFN);
    k_moe_up<<<CK_T,256>>>(p_d2, p_v2, eB2, p_route, p_fpre);
    k_hgemm2<<<dim3(CK_D/128, CK_T/128),256,HG_SMEM>>>(gs_h, gs_l, w2_h, w2_l, out, CK_T, CK_D, CK_FFN, nullptr, nullptr, 0.f, p_fpre);
}

// round 8
// speedup vs baseline: 2.7630x; 1.3509x over previous
#include <cuda_runtime.h>
#include <cuda_fp16.h>
#include <math.h>
#include <stdint.h>

#define CK_B   4
#define CK_S   512
#define CK_D   2048
#define CK_H   16
#define CK_KV  4
#define CK_HD  128
#define CK_T   2048          // B*S
#define CK_FFN 5632
#define CK_E   8
#define CK_R   16
#define CK_LS  2.0f          // 32/16

// ---------------------------------------------------------------------------
// fp32 scratch
// ---------------------------------------------------------------------------
__device__ float g_h   [CK_T*CK_D];
__device__ float g_hn  [CK_T*CK_D];
__device__ float g_xq  [CK_T*CK_D];
__device__ float g_xk  [CK_T*CK_KV*CK_HD];
__device__ float g_xv  [CK_T*CK_KV*CK_HD];
__device__ float g_sc  [(size_t)CK_B*CK_H*CK_S*CK_S];
__device__ float g_ao  [CK_T*CK_D];
__device__ float g_d2  [CK_T*CK_D];
__device__ float g_uq  [CK_T*CK_R];
__device__ float g_uk  [CK_T*CK_R];
__device__ float g_uv  [CK_T*CK_R];
__device__ float g_uo  [CK_T*CK_R];
__device__ float g_route[CK_T*CK_E];
__device__ float g_ua1 [CK_T*CK_E*CK_R];
__device__ float g_ua3 [CK_T*CK_E*CK_R];
__device__ float g_h1  [(size_t)CK_T*CK_FFN];
__device__ float g_h3  [(size_t)CK_T*CK_FFN];
__device__ float g_v2  [CK_T*CK_E*CK_R];
__device__ float g_fpre[CK_T*CK_D];

// ---------------------------------------------------------------------------
// fp16 scratch: weights split hi/lo, activations single fp16
// ---------------------------------------------------------------------------
#define NWQ (CK_D*CK_D)
#define NWK (512*CK_D)
#define NW1 (CK_FFN*CK_D)
#define NEB (CK_E*CK_FFN*CK_R)   // 720896
#define NB2 (CK_E*CK_D*CK_R)     // 262144
__device__ __align__(16) __half g_wq_h[NWQ],  g_wq_l[NWQ];
__device__ __align__(16) __half g_wk_h[NWK],  g_wk_l[NWK];
__device__ __align__(16) __half g_wv_h[NWK],  g_wv_l[NWK];
__device__ __align__(16) __half g_wo_h[NWQ],  g_wo_l[NWQ];
__device__ __align__(16) __half g_w1_h[NW1],  g_w1_l[NW1];
__device__ __align__(16) __half g_w3_h[NW1],  g_w3_l[NW1];
__device__ __align__(16) __half g_w2_h[NW1],  g_w2_l[NW1];
__device__ __align__(16) __half g_xh [CK_T*CK_D];                // h  fp16
__device__ __align__(16) __half g_aoh[CK_T*CK_D];                // ao fp16
__device__ __align__(16) __half g_hnh[CK_T*CK_D];                // hn fp16
__device__ __align__(16) __half g_gsh[(size_t)CK_T*CK_FFN];      // ghs fp16
__device__ __align__(16) __half g_eB1h[NEB], g_eB3h[NEB], g_eA2h[NEB];
__device__ __align__(16) __half g_eB2h[NB2];

// ===========================================================================
// helpers
// ===========================================================================
__device__ __forceinline__ uint32_t smem_u32(const void* p) {
    uint32_t a;
    asm("{ .reg .u64 t; cvta.to.shared.u64 t, %1; cvt.u32.u64 %0, t; }" : "=r"(a) : "l"(p));
    return a;
}
#define CP_ASYNC16(dst_u32, src_ptr) \
    asm volatile("cp.async.cg.shared.global [%0], [%1], 16;" :: "r"(dst_u32), "l"(src_ptr))
#define CP_COMMIT() asm volatile("cp.async.commit_group;" ::: "memory")
#define CP_WAIT(n)  asm volatile("cp.async.wait_group %0;" :: "n"(n) : "memory")

__device__ __forceinline__ void mma16816(float* d, const uint32_t* a,
                                         uint32_t b0, uint32_t b1) {
    asm volatile(
        "mma.sync.aligned.m16n8k16.row.col.f32.f16.f16.f32 "
        "{%0,%1,%2,%3}, {%4,%5,%6,%7}, {%8,%9}, {%0,%1,%2,%3};"
        : "+f"(d[0]), "+f"(d[1]), "+f"(d[2]), "+f"(d[3])
        : "r"(a[0]), "r"(a[1]), "r"(a[2]), "r"(a[3]), "r"(b0), "r"(b1));
}

__device__ __forceinline__ void store4h(__half* p, float4 v) {
    *(__half2*)(p + 0) = __floats2half2_rn(v.x, v.y);
    *(__half2*)(p + 2) = __floats2half2_rn(v.z, v.w);
}

// fp32 -> fp16 hi + fp16 lo, 8 elems/thread (weights)
__global__ void k_wsplit(const float* __restrict__ x, __half* __restrict__ h,
                         __half* __restrict__ l, int n) {
    int i = (blockIdx.x*256 + threadIdx.x)*8;
    if (i >= n) return;
    #pragma unroll
    for (int q = 0; q < 2; q++) {
        float4 v = *(const float4*)(x + i + q*4);
        float vs[4] = {v.x, v.y, v.z, v.w};
        __half hh[4], ll[4];
        #pragma unroll
        for (int j = 0; j < 4; j++) {
            hh[j] = __float2half_rn(vs[j]);
            ll[j] = __float2half_rn(vs[j] - __half2float(hh[j]));
        }
        *(__half2*)(h + i + q*4)     = __halves2half2(hh[0], hh[1]);
        *(__half2*)(h + i + q*4 + 2) = __halves2half2(hh[2], hh[3]);
        *(__half2*)(l + i + q*4)     = __halves2half2(ll[0], ll[1]);
        *(__half2*)(l + i + q*4 + 2) = __halves2half2(ll[2], ll[3]);
    }
}

// fp32 -> fp16, 4 elems/thread (expert LoRA mats)
__global__ void k_half(const float* __restrict__ x, __half* __restrict__ h, int n) {
    int i = (blockIdx.x*256 + threadIdx.x)*4;
    if (i >= n) return;
    float4 v = *(const float4*)(x + i);
    store4h(h + i, v);
}

// ===========================================================================
// k_hgemm3: 2-pass fp16 tensor-core GEMM, cp.async double-buffered
//   C = A @ (Wh+Wl)^T [+ lscale*U@V^T] [+ res]
//   A single fp16; W pre-split hi/lo fp16. Tiles 128x128x32, 8 warps (4x2).
// ===========================================================================
#define HG_LD   40
#define HG_TILE (128*HG_LD)
#define HG_TILEB (HG_TILE*2)
#define HG_SMEM (6*HG_TILEB)      // 61440 bytes

__global__ void __launch_bounds__(256, 2) k_hgemm3(
    const __half* __restrict__ A,
    const __half* __restrict__ Wh, const __half* __restrict__ Wl,
    float* __restrict__ C, int M, int N, int K,
    const float* __restrict__ U, const float* __restrict__ V, float lscale,
    const float* __restrict__ res)
{
    extern __shared__ __align__(16) __half sm[];
    __half* pA  = sm;                    // 2 bufs
    __half* pWh = sm + 2*HG_TILE;        // 2 bufs
    __half* pWl = sm + 4*HG_TILE;        // 2 bufs
    const uint32_t sb   = smem_u32(sm);
    const uint32_t sbA  = sb;
    const uint32_t sbWh = sb + 2*HG_TILEB;
    const uint32_t sbWl = sb + 4*HG_TILEB;

    const int tid  = threadIdx.x;
    const int wid  = tid >> 5, lane = tid & 31;
    const int g    = lane >> 2, tg = lane & 3;
    const int warpM = wid & 3;
    const int warpN = wid >> 2;
    const int bm = blockIdx.y * 128;
    const int bn = blockIdx.x * 128;

    float acc[2][8][4];
    #pragma unroll
    for (int mi = 0; mi < 2; mi++)
        #pragma unroll
        for (int ni = 0; ni < 8; ni++)
            #pragma unroll
            for (int q = 0; q < 4; q++) acc[mi][ni][q] = 0.f;

    const int NC = K / 32;
    const int total = NC + (U ? 1 : 0);

    auto load_async = [&](int c, int buf) {
        const int k0 = c * 32;
        const uint32_t bo = (uint32_t)buf * HG_TILEB;
        #pragma unroll
        for (int it = 0; it < 2; it++) {
            int id = it*256 + tid;
            int r = id >> 2, sg = (id & 3) * 8;
            uint32_t so = bo + (uint32_t)(r*HG_LD + sg)*2;
            size_t ga = (size_t)(bm + r)*K + k0 + sg;
            size_t gw = (size_t)(bn + r)*K + k0 + sg;
            CP_ASYNC16(sbA  + so, A  + ga);
            CP_ASYNC16(sbWh + so, Wh + gw);
            CP_ASYNC16(sbWl + so, Wl + gw);
        }
        CP_COMMIT();
    };

    auto load_lora = [&](int buf) {
        __half* dA  = pA  + buf*HG_TILE;
        __half* dWh = pWh + buf*HG_TILE;
        __half* dWl = pWl + buf*HG_TILE;
        #pragma unroll
        for (int l = 0; l < 4; l++) {
            int id = l*256 + tid;
            int r = id >> 3, c4 = (id & 7)*4;
            float4 va = make_float4(0.f,0.f,0.f,0.f);
            float4 vw = make_float4(0.f,0.f,0.f,0.f);
            if (c4 < 16) {
                va = *(const float4*)(U + (size_t)(bm + r)*16 + c4);
                va.x *= lscale; va.y *= lscale; va.z *= lscale; va.w *= lscale;
                vw = *(const float4*)(V + (size_t)(bn + r)*16 + c4);
            }
            store4h(dA  + r*HG_LD + c4, va);
            store4h(dWh + r*HG_LD + c4, vw);
            store4h(dWl + r*HG_LD + c4, make_float4(0.f,0.f,0.f,0.f));
        }
    };

    load_async(0, 0);

    for (int c = 0; c < total; c++) {
        const int cur = c & 1, nb = (c + 1) & 1;
        const bool have_next = (c + 1 < total);
        const bool next_async = (c + 1 < NC);
        if (have_next) {
            if (next_async) load_async(c + 1, nb);
            else            load_lora(nb);
        }
        if (c < NC) {
            if (have_next && next_async) { CP_WAIT(1); }
            else                         { CP_WAIT(0); }
        }
        __syncthreads();

        const __half* bA  = pA  + cur*HG_TILE;
        const __half* bWh = pWh + cur*HG_TILE;
        const __half* bWl = pWl + cur*HG_TILE;

        #pragma unroll
        for (int ks = 0; ks < 2; ks++) {
            const int col0 = ks*16 + tg*2;
            uint32_t a[2][4];
            #pragma unroll
            for (int mi = 0; mi < 2; mi++) {
                int r0 = warpM*32 + mi*16 + g;
                a[mi][0] = *(const uint32_t*)(bA + r0*HG_LD + col0);
                a[mi][1] = *(const uint32_t*)(bA + (r0+8)*HG_LD + col0);
                a[mi][2] = *(const uint32_t*)(bA + r0*HG_LD + col0 + 8);
                a[mi][3] = *(const uint32_t*)(bA + (r0+8)*HG_LD + col0 + 8);
            }
            #pragma unroll
            for (int ni = 0; ni < 8; ni++) {
                int rn = warpN*64 + ni*8 + g;
                uint32_t bh0 = *(const uint32_t*)(bWh + rn*HG_LD + col0);
                uint32_t bh1 = *(const uint32_t*)(bWh + rn*HG_LD + col0 + 8);
                uint32_t bl0 = *(const uint32_t*)(bWl + rn*HG_LD + col0);
                uint32_t bl1 = *(const uint32_t*)(bWl + rn*HG_LD + col0 + 8);
                #pragma unroll
                for (int mi = 0; mi < 2; mi++) {
                    mma16816(acc[mi][ni], a[mi], bh0, bh1);
                    mma16816(acc[mi][ni], a[mi], bl0, bl1);
                }
            }
        }
        __syncthreads();
    }

    #pragma unroll
    for (int mi = 0; mi < 2; mi++) {
        size_t r0 = (size_t)(bm + warpM*32 + mi*16 + g);
        #pragma unroll
        for (int ni = 0; ni < 8; ni++) {
            size_t c0 = (size_t)(bn + warpN*64 + ni*8 + tg*2);
            float2 o0 = make_float2(acc[mi][ni][0], acc[mi][ni][1]);
            float2 o1 = make_float2(acc[mi][ni][2], acc[mi][ni][3]);
            if (res) {
                float2 r0v = *(const float2*)(res + r0*N + c0);
                float2 r1v = *(const float2*)(res + (r0+8)*N + c0);
                o0.x += r0v.x; o0.y += r0v.y;
                o1.x += r1v.x; o1.y += r1v.y;
            }
            *(float2*)(C + r0*N + c0)     = o0;
            *(float2*)(C + (r0+8)*N + c0) = o1;
        }
    }
}

// ---------------------------------------------------------------------------
// RMSNorm (fp32 out + fp16 out)
// ---------------------------------------------------------------------------
__global__ void k_rmsnorm(const float* __restrict__ x, const float* __restrict__ w,
                          float* __restrict__ o, __half* __restrict__ oh) {
    int t = blockIdx.x;
    const float* xr = x + (size_t)t*CK_D;
    float ss = 0.f;
    for (int i = threadIdx.x; i < CK_D; i += 256) { float v = xr[i]; ss += v*v; }
    __shared__ float red[256];
    red[threadIdx.x] = ss; __syncthreads();
    for (int s = 128; s > 0; s >>= 1) {
        if (threadIdx.x < s) red[threadIdx.x] += red[threadIdx.x+s];
        __syncthreads();
    }
    float sc = rsqrtf(red[0]/(float)CK_D + 1e-5f);
    float* orow = o + (size_t)t*CK_D;
    __half* hrow = oh + (size_t)t*CK_D;
    for (int i = threadIdx.x; i < CK_D; i += 256) {
        float r = xr[i]*sc*w[i];
        orow[i] = r;
        hrow[i] = __float2half_rn(r);
    }
}

// ---------------------------------------------------------------------------
// LoRA down-projection
// ---------------------------------------------------------------------------
__global__ void k_lora_down(const float* __restrict__ X, const float* __restrict__ A,
                            float* __restrict__ U) {
    int t = blockIdx.x;
    __shared__ float sx[CK_D];
    for (int i = threadIdx.x; i < CK_D; i += 256) sx[i] = X[(size_t)t*CK_D + i];
    __syncthreads();
    int w = threadIdx.x >> 5, lane = threadIdx.x & 31;
    for (int r = w; r < CK_R; r += 8) {
        const float* ar = A + (size_t)r*CK_D;
        float p = 0.f;
        for (int d = lane; d < CK_D; d += 32) p += sx[d]*ar[d];
        for (int o = 16; o; o >>= 1) p += __shfl_down_sync(0xffffffffu, p, o);
        if (lane == 0) U[t*CK_R + r] = p;
    }
}

// ---------------------------------------------------------------------------
// RoPE (in place)
// ---------------------------------------------------------------------------
__global__ void k_rope(float* __restrict__ x, const float* __restrict__ cs,
                       const float* __restrict__ sn, int nh, int total) {
    int i = blockIdx.x*256 + threadIdx.x;
    if (i >= total) return;
    int d2 = i & 63;
    int h  = (i >> 6) % nh;
    int t  = i / (64*nh);
    int s  = t & (CK_S - 1);
    float c  = cs[s*64 + d2];
    float si = sn[s*64 + d2];
    float* p = x + ((size_t)t*nh + h)*CK_HD + 2*d2;
    float x1 = p[0], x2 = p[1];
    p[0] = x1*c - x2*si;
    p[1] = x1*si + x2*c;
}

// ---------------------------------------------------------------------------
// scores (upper-triangle tiles skipped)
// ---------------------------------------------------------------------------
__global__ void __launch_bounds__(256) k_scores(const float* __restrict__ xq,
                                                const float* __restrict__ xk,
                                                float* __restrict__ sc) {
    const int t0 = blockIdx.x*64, s0 = blockIdx.y*64;
    if (t0 > s0 + 63) return;
    const int bh = blockIdx.z, b = bh >> 4, h = bh & 15, kv = h >> 2;
    const float* Q  = xq + ((size_t)b*CK_S*CK_H  + h )*CK_HD;
    const float* Kp = xk + ((size_t)b*CK_S*CK_KV + kv)*CK_HD;
    __shared__ float Qs[16][64], Ks[16][64];
    const int tid = threadIdx.x;
    const int lrow = tid >> 2, lk = (tid & 3)*4;
    const int ty = tid >> 4, tx = tid & 15;
    float acc[4][4];
    #pragma unroll
    for (int i=0;i<4;i++)
        #pragma unroll
        for (int j=0;j<4;j++) acc[i][j]=0.f;

    for (int k0 = 0; k0 < CK_HD; k0 += 16) {
        float4 q4 = *(const float4*)(Q  + (size_t)(s0+lrow)*(CK_H*CK_HD)  + k0 + lk);
        Qs[lk+0][lrow]=q4.x; Qs[lk+1][lrow]=q4.y; Qs[lk+2][lrow]=q4.z; Qs[lk+3][lrow]=q4.w;
        float4 k4 = *(const float4*)(Kp + (size_t)(t0+lrow)*(CK_KV*CK_HD) + k0 + lk);
        Ks[lk+0][lrow]=k4.x; Ks[lk+1][lrow]=k4.y; Ks[lk+2][lrow]=k4.z; Ks[lk+3][lrow]=k4.w;
        __syncthreads();
        #pragma unroll
        for (int k = 0; k < 16; k++) {
            float4 a  = *(const float4*)&Qs[k][ty*4];
            float4 bb = *(const float4*)&Ks[k][tx*4];
            float ra[4] = {a.x,a.y,a.z,a.w};
            float rb[4] = {bb.x,bb.y,bb.z,bb.w};
            #pragma unroll
            for (int i=0;i<4;i++)
                #pragma unroll
                for (int j=0;j<4;j++) acc[i][j] += ra[i]*rb[j];
        }
        __syncthreads();
    }
    const float scl = 0.08838834764831845f;
    float* out = sc + (size_t)bh*CK_S*CK_S;
    #pragma unroll
    for (int i = 0; i < 4; i++) {
        size_t srow = (size_t)(s0 + ty*4 + i);
        float4 o;
        o.x=acc[i][0]*scl; o.y=acc[i][1]*scl; o.z=acc[i][2]*scl; o.w=acc[i][3]*scl;
        *(float4*)(out + srow*CK_S + t0 + tx*4) = o;
    }
}

// ---------------------------------------------------------------------------
// Causal softmax, single pass
// ---------------------------------------------------------------------------
__global__ void k_softmax(float* __restrict__ sc) {
    int row = blockIdx.x;            // bh*512 + s
    int s = row & (CK_S - 1);
    float* p = sc + (size_t)row*CK_S;
    int L = s + 1;
    int tid = threadIdx.x;
    float v0 = (tid       < L) ? p[tid]       : -1e30f;
    float v1 = (tid + 256 < L) ? p[tid + 256] : -1e30f;
    __shared__ float red[256];
    red[tid] = fmaxf(v0, v1); __syncthreads();
    for (int st = 128; st; st >>= 1) {
        if (tid < st) red[tid] = fmaxf(red[tid], red[tid+st]);
        __syncthreads();
    }
    float m = red[0]; __syncthreads();
    float e0 = (tid       < L) ? expf(v0 - m) : 0.f;
    float e1 = (tid + 256 < L) ? expf(v1 - m) : 0.f;
    red[tid] = e0 + e1; __syncthreads();
    for (int st = 128; st; st >>= 1) {
        if (tid < st) red[tid] += red[tid+st];
        __syncthreads();
    }
    float inv = 1.f / red[0];
    p[tid]       = e0 * inv;
    p[tid + 256] = e1 * inv;
}

// ---------------------------------------------------------------------------
// out = attn @ V  (causal: K-loop only up to s0+64), fp32 + fp16 outputs
// ---------------------------------------------------------------------------
__global__ void __launch_bounds__(256) k_av(const float* __restrict__ attn,
                                            const float* __restrict__ xv,
                                            float* __restrict__ out,
                                            __half* __restrict__ outh) {
    const int s0 = blockIdx.x*64;
    const int bh = blockIdx.z, b = bh >> 4, h = bh & 15, kv = h >> 2;
    const float* Ab = attn + (size_t)bh*CK_S*CK_S;
    const float* Vb = xv + ((size_t)b*CK_S*CK_KV + kv)*CK_HD;
    __shared__ float As[64][33];
    __shared__ float Vs[32][128];
    const int tid = threadIdx.x;
    const int ty = tid >> 5, tx = tid & 31;
    float acc[8][4];
    #pragma unroll
    for (int i=0;i<8;i++)
        #pragma unroll
        for (int j=0;j<4;j++) acc[i][j]=0.f;

    const int kmax = s0 + 64;            // attn is zero beyond the diagonal
    for (int k0 = 0; k0 < kmax; k0 += 32) {
        #pragma unroll
        for (int l = 0; l < 2; l++) {
            int id = tid + l*256, r = id >> 3, c4 = (id & 7)*4;
            float4 a = *(const float4*)(Ab + (size_t)(s0+r)*CK_S + k0 + c4);
            As[r][c4]=a.x; As[r][c4+1]=a.y; As[r][c4+2]=a.z; As[r][c4+3]=a.w;
        }
        #pragma unroll
        for (int l = 0; l < 4; l++) {
            int id = tid + l*256, r = id >> 5, c4 = (id & 31)*4;
            float4 v = *(const float4*)(Vb + (size_t)(k0+r)*(CK_KV*CK_HD) + c4);
            *(float4*)&Vs[r][c4] = v;
        }
        __syncthreads();
        #pragma unroll
        for (int k = 0; k < 32; k++) {
            float4 vv = *(const float4*)&Vs[k][tx*4];
            #pragma unroll
            for (int i = 0; i < 8; i++) {
                float a = As[ty*8+i][k];
                acc[i][0]+=a*vv.x; acc[i][1]+=a*vv.y; acc[i][2]+=a*vv.z; acc[i][3]+=a*vv.w;
            }
        }
        __syncthreads();
    }
    #pragma unroll
    for (int i = 0; i < 8; i++) {
        int s = s0 + ty*8 + i;
        size_t off = ((size_t)(b*CK_S+s)*CK_H + h)*CK_HD + tx*4;
        float4 o; o.x=acc[i][0]; o.y=acc[i][1]; o.z=acc[i][2]; o.w=acc[i][3];
        *(float4*)(out + off) = o;
        store4h(outh + off, o);
    }
}

// ---------------------------------------------------------------------------
// Gate
// ---------------------------------------------------------------------------
__global__ void k_gate(const float* __restrict__ hn, const float* __restrict__ gw,
                       float* __restrict__ route) {
    int t = blockIdx.x;
    __shared__ float sl[8];
    int w = threadIdx.x >> 5, lane = threadIdx.x & 31;
    const float* xr = hn + (size_t)t*CK_D;
    const float* gr = gw + (size_t)w*CK_D;
    float p = 0.f;
    for (int d = lane; d < CK_D; d += 32) p += xr[d]*gr[d];
    for (int o = 16; o; o >>= 1) p += __shfl_down_sync(0xffffffffu, p, o);
    if (lane == 0) sl[w] = p;
    __syncthreads();
    if (threadIdx.x == 0) {
        int i0 = 0;
        for (int e = 1; e < 8; e++) if (sl[e] > sl[i0]) i0 = e;
        int i1 = -1;
        for (int e = 0; e < 8; e++) { if (e == i0) continue; if (i1 < 0 || sl[e] > sl[i1]) i1 = e; }
        float m = sl[i0];
        float v0 = expf(sl[i0]-m), v1 = expf(sl[i1]-m);
        float inv = 1.f/(v0+v1);
        float* rr = route + (size_t)t*CK_E;
        #pragma unroll
        for (int e = 0; e < 8; e++) rr[e] = 0.f;
        rr[i0] = v0*inv; rr[i1] = v1*inv;
    }
}

// ---------------------------------------------------------------------------
// Expert LoRA downs
// ---------------------------------------------------------------------------
__global__ void k_expert_down(const float* __restrict__ X, const float* __restrict__ A1,
                              const float* __restrict__ A3, const float* __restrict__ route,
                              float* __restrict__ U1, float* __restrict__ U3) {
    int t = blockIdx.x, e = blockIdx.y;
    if (route[t*CK_E + e] == 0.f) return;
    __shared__ float sx[CK_D];
    for (int i = threadIdx.x; i < CK_D; i += 256) sx[i] = X[(size_t)t*CK_D + i];
    __syncthreads();
    int w = threadIdx.x >> 5, lane = threadIdx.x & 31;
    const float* a1 = A1 + (size_t)e*CK_R*CK_D;
    const float* a3 = A3 + (size_t)e*CK_R*CK_D;
    for (int r = w; r < CK_R; r += 8) {
        float p1 = 0.f, p3 = 0.f;
        for (int d = lane; d < CK_D; d += 32) {
            float xv = sx[d];
            p1 += xv*a1[(size_t)r*CK_D + d];
            p3 += xv*a3[(size_t)r*CK_D + d];
        }
        for (int o = 16; o; o >>= 1) {
            p1 += __shfl_down_sync(0xffffffffu, p1, o);
            p3 += __shfl_down_sync(0xffffffffu, p3, o);
        }
        if (lane == 0) {
            U1[((size_t)t*CK_E + e)*CK_R + r] = p1;
            U3[((size_t)t*CK_E + e)*CK_R + r] = p3;
        }
    }
}

// ---------------------------------------------------------------------------
// Fused per-token MoE combine; expert mats in fp16, ghs out fp16
// ---------------------------------------------------------------------------
__device__ __forceinline__ void h8f(const __half* p, float* f) {
    uint4 q = *(const uint4*)p;
    const __half2* hp = (const __half2*)&q;
    #pragma unroll
    for (int j = 0; j < 4; j++) {
        float2 t = __half22float2(hp[j]);
        f[2*j] = t.x; f[2*j+1] = t.y;
    }
}

__global__ void __launch_bounds__(256) k_moe_expert(
    const float* __restrict__ h1, const float* __restrict__ h3,
    const float* __restrict__ ua1, const float* __restrict__ ua3,
    const __half* __restrict__ eB1, const __half* __restrict__ eB3,
    const __half* __restrict__ eA2, const float* __restrict__ route,
    __half* __restrict__ ghs, float* __restrict__ v2)
{
    const int t = blockIdx.x;
    const int tid = threadIdx.x;
    const int wid = tid >> 5, lane = tid & 31;
    const int NI = CK_FFN/256;   // 22
    float ghacc[CK_FFN/256];
    #pragma unroll
    for (int i = 0; i < NI; i++) ghacc[i] = 0.f;
    __shared__ float su1[16], su3[16];
    __shared__ float part[8][16];
    const float* h1r = h1 + (size_t)t*CK_FFN;
    const float* h3r = h3 + (size_t)t*CK_FFN;

    #pragma unroll 1
    for (int e = 0; e < CK_E; e++) {
        float wgt = route[t*CK_E + e];
        if (wgt == 0.f) {
            if (tid < 16) v2[(size_t)t*(CK_E*CK_R) + e*16 + tid] = 0.f;
            continue;
        }
        if (tid < 16) {
            su1[tid] = ua1[((size_t)t*CK_E + e)*16 + tid];
            su3[tid] = ua3[((size_t)t*CK_E + e)*16 + tid];
        }
        __syncthreads();
        float u1[16], u3[16];
        #pragma unroll
        for (int r = 0; r < 16; r++) { u1[r] = su1[r]; u3[r] = su3[r]; }
        float accr[16];
        #pragma unroll
        for (int r = 0; r < 16; r++) accr[r] = 0.f;
        const __half* B1 = eB1 + (size_t)e*CK_FFN*16;
        const __half* B3 = eB3 + (size_t)e*CK_FFN*16;
        const __half* A2 = eA2 + (size_t)e*16*CK_FFN;
        #pragma unroll
        for (int ii = 0; ii < NI; ii++) {
            int f = ii*256 + tid;
            float b1v[16], b3v[16];
            h8f(B1 + (size_t)f*16,     b1v);
            h8f(B1 + (size_t)f*16 + 8, b1v + 8);
            h8f(B3 + (size_t)f*16,     b3v);
            h8f(B3 + (size_t)f*16 + 8, b3v + 8);
            float b1 = 0.f, b3 = 0.f;
            #pragma unroll
            for (int r = 0; r < 16; r++) { b1 += u1[r]*b1v[r]; b3 += u3[r]*b3v[r]; }
            float g1 = h1r[f] + CK_LS*b1;
            float g3 = h3r[f] + CK_LS*b3;
            float gh = (g1/(1.f + expf(-g1)))*g3;
            ghacc[ii] += wgt*gh;
            #pragma unroll
            for (int r = 0; r < 16; r++)
                accr[r] += gh * __half2float(A2[(size_t)r*CK_FFN + f]);
        }
        #pragma unroll
        for (int r = 0; r < 16; r++) {
            float v = accr[r];
            #pragma unroll
            for (int o = 16; o; o >>= 1) v += __shfl_down_sync(0xffffffffu, v, o);
            if (lane == 0) part[wid][r] = v;
        }
        __syncthreads();
        if (tid < 16) {
            float s2 = 0.f;
            #pragma unroll
            for (int ww = 0; ww < 8; ww++) s2 += part[ww][tid];
            v2[(size_t)t*(CK_E*CK_R) + e*16 + tid] = wgt*CK_LS*s2;
        }
        __syncthreads();
    }
    __half* go = ghs + (size_t)t*CK_FFN;
    #pragma unroll
    for (int ii = 0; ii < NI; ii++) go[ii*256 + tid] = __float2half_rn(ghacc[ii]);
}

// ---------------------------------------------------------------------------
// fpre = data2 + v2 @ eB2^T  (eB2 in fp16)
// ---------------------------------------------------------------------------
__global__ void k_moe_up(const float* __restrict__ d2, const float* __restrict__ v2,
                         const __half* __restrict__ eB2, const float* __restrict__ route,
                         float* __restrict__ out) {
    int t = blockIdx.x, tid = threadIdx.x;
    __shared__ float sv[128];
    __shared__ int act[8];
    if (tid < 128) sv[tid] = v2[(size_t)t*128 + tid];
    if (tid < 8)   act[tid] = (route[t*CK_E + tid] != 0.f) ? 1 : 0;
    __syncthreads();
    for (int d = tid; d < CK_D; d += 256) {
        float s = d2[(size_t)t*CK_D + d];
        #pragma unroll 1
        for (int e = 0; e < 8; e++) {
            if (!act[e]) continue;
            float bv[16];
            const __half* bp = eB2 + ((size_t)e*CK_D + d)*16;
            h8f(bp, bv); h8f(bp + 8, bv + 8);
            #pragma unroll
            for (int r = 0; r < 16; r++) s += sv[e*16+r]*bv[r];
        }
        out[(size_t)t*CK_D + d] = s;
    }
}

// ---------------------------------------------------------------------------
// Launch
// ---------------------------------------------------------------------------
extern "C" void kernel_launch(void* const* d_in, const int* in_sizes, int n_in,
                              void* d_out, int out_size) {
    (void)in_sizes; (void)n_in; (void)out_size;
    const float* data  = (const float*)d_in[0];
    const float* rc    = (const float*)d_in[2];
    const float* rs    = (const float*)d_in[3];
    const float* att_w = (const float*)d_in[4];
    const float* ffn_w = (const float*)d_in[5];
    const float* wq    = (const float*)d_in[6];
    const float* wk    = (const float*)d_in[7];
    const float* wv    = (const float*)d_in[8];
    const float* wo    = (const float*)d_in[9];
    const float* lqA   = (const float*)d_in[10];
    const float* lqB   = (const float*)d_in[11];
    const float* lkA   = (const float*)d_in[12];
    const float* lkB   = (const float*)d_in[13];
    const float* lvA   = (const float*)d_in[14];
    const float* lvB   = (const float*)d_in[15];
    const float* loA   = (const float*)d_in[16];
    const float* loB   = (const float*)d_in[17];
    const float* w1    = (const float*)d_in[18];
    const float* w2    = (const float*)d_in[19];
    const float* w3    = (const float*)d_in[20];
    const float* gatew = (const float*)d_in[21];
    const float* eA1   = (const float*)d_in[22];
    const float* eB1   = (const float*)d_in[23];
    const float* eA2   = (const float*)d_in[24];
    const float* eB2   = (const float*)d_in[25];
    const float* eA3   = (const float*)d_in[26];
    const float* eB3   = (const float*)d_in[27];
    float* out = (float*)d_out;

    float *p_h,*p_hn,*p_xq,*p_xk,*p_xv,*p_sc,*p_ao,*p_d2,*p_uq,*p_uk,*p_uv,*p_uo;
    float *p_route,*p_ua1,*p_ua3,*p_h1,*p_h3,*p_v2,*p_fpre;
    cudaGetSymbolAddress((void**)&p_h,    g_h);
    cudaGetSymbolAddress((void**)&p_hn,   g_hn);
    cudaGetSymbolAddress((void**)&p_xq,   g_xq);
    cudaGetSymbolAddress((void**)&p_xk,   g_xk);
    cudaGetSymbolAddress((void**)&p_xv,   g_xv);
    cudaGetSymbolAddress((void**)&p_sc,   g_sc);
    cudaGetSymbolAddress((void**)&p_ao,   g_ao);
    cudaGetSymbolAddress((void**)&p_d2,   g_d2);
    cudaGetSymbolAddress((void**)&p_uq,   g_uq);
    cudaGetSymbolAddress((void**)&p_uk,   g_uk);
    cudaGetSymbolAddress((void**)&p_uv,   g_uv);
    cudaGetSymbolAddress((void**)&p_uo,   g_uo);
    cudaGetSymbolAddress((void**)&p_route,g_route);
    cudaGetSymbolAddress((void**)&p_ua1,  g_ua1);
    cudaGetSymbolAddress((void**)&p_ua3,  g_ua3);
    cudaGetSymbolAddress((void**)&p_h1,   g_h1);
    cudaGetSymbolAddress((void**)&p_h3,   g_h3);
    cudaGetSymbolAddress((void**)&p_v2,   g_v2);
    cudaGetSymbolAddress((void**)&p_fpre, g_fpre);

    __half *wq_h,*wq_l,*wk_h,*wk_l,*wv_h,*wv_l,*wo_h,*wo_l;
    __half *w1_h,*w1_l,*w3_h,*w3_l,*w2_h,*w2_l;
    __half *xh,*aoh,*hnh,*gsh,*eB1h,*eB3h,*eA2h,*eB2h;
    cudaGetSymbolAddress((void**)&wq_h, g_wq_h); cudaGetSymbolAddress((void**)&wq_l, g_wq_l);
    cudaGetSymbolAddress((void**)&wk_h, g_wk_h); cudaGetSymbolAddress((void**)&wk_l, g_wk_l);
    cudaGetSymbolAddress((void**)&wv_h, g_wv_h); cudaGetSymbolAddress((void**)&wv_l, g_wv_l);
    cudaGetSymbolAddress((void**)&wo_h, g_wo_h); cudaGetSymbolAddress((void**)&wo_l, g_wo_l);
    cudaGetSymbolAddress((void**)&w1_h, g_w1_h); cudaGetSymbolAddress((void**)&w1_l, g_w1_l);
    cudaGetSymbolAddress((void**)&w3_h, g_w3_h); cudaGetSymbolAddress((void**)&w3_l, g_w3_l);
    cudaGetSymbolAddress((void**)&w2_h, g_w2_h); cudaGetSymbolAddress((void**)&w2_l, g_w2_l);
    cudaGetSymbolAddress((void**)&xh,  g_xh);   cudaGetSymbolAddress((void**)&aoh, g_aoh);
    cudaGetSymbolAddress((void**)&hnh, g_hnh);  cudaGetSymbolAddress((void**)&gsh, g_gsh);
    cudaGetSymbolAddress((void**)&eB1h, g_eB1h); cudaGetSymbolAddress((void**)&eB3h, g_eB3h);
    cudaGetSymbolAddress((void**)&eA2h, g_eA2h); cudaGetSymbolAddress((void**)&eB2h, g_eB2h);

    cudaFuncSetAttribute(k_hgemm3, cudaFuncAttributeMaxDynamicSharedMemorySize, HG_SMEM);

    // --- weight/expert-mat conversions ---
    k_wsplit<<<NWQ/2048,256>>>(wq, wq_h, wq_l, NWQ);
    k_wsplit<<<NWK/2048,256>>>(wk, wk_h, wk_l, NWK);
    k_wsplit<<<NWK/2048,256>>>(wv, wv_h, wv_l, NWK);
    k_wsplit<<<NWQ/2048,256>>>(wo, wo_h, wo_l, NWQ);
    k_wsplit<<<NW1/2048,256>>>(w1, w1_h, w1_l, NW1);
    k_wsplit<<<NW1/2048,256>>>(w3, w3_h, w3_l, NW1);
    k_wsplit<<<NW1/2048,256>>>(w2, w2_h, w2_l, NW1);
    k_half<<<NEB/1024,256>>>(eB1, eB1h, NEB);
    k_half<<<NEB/1024,256>>>(eB3, eB3h, NEB);
    k_half<<<NEB/1024,256>>>(eA2, eA2h, NEB);
    k_half<<<NB2/1024,256>>>(eB2, eB2h, NB2);

    // --- attention path ---
    k_rmsnorm<<<CK_T,256>>>(data, att_w, p_h, xh);
    k_lora_down<<<CK_T,256>>>(p_h, lqA, p_uq);
    k_lora_down<<<CK_T,256>>>(p_h, lkA, p_uk);
    k_lora_down<<<CK_T,256>>>(p_h, lvA, p_uv);
    k_hgemm3<<<dim3(CK_D/128, CK_T/128),256,HG_SMEM>>>(xh, wq_h, wq_l, p_xq, CK_T, CK_D, CK_D, p_uq, lqB, CK_LS, nullptr);
    k_hgemm3<<<dim3(512/128,  CK_T/128),256,HG_SMEM>>>(xh, wk_h, wk_l, p_xk, CK_T, 512,  CK_D, p_uk, lkB, CK_LS, nullptr);
    k_hgemm3<<<dim3(512/128,  CK_T/128),256,HG_SMEM>>>(xh, wv_h, wv_l, p_xv, CK_T, 512,  CK_D, p_uv, lvB, CK_LS, nullptr);
    k_rope<<<(CK_T*CK_H*64 + 255)/256, 256>>>(p_xq, rc, rs, CK_H,  CK_T*CK_H*64);
    k_rope<<<(CK_T*CK_KV*64 + 255)/256,256>>>(p_xk, rc, rs, CK_KV, CK_T*CK_KV*64);
    k_scores<<<dim3(CK_S/64, CK_S/64, CK_B*CK_H),256>>>(p_xq, p_xk, p_sc);
    k_softmax<<<CK_B*CK_H*CK_S,256>>>(p_sc);
    k_av<<<dim3(CK_S/64, 1, CK_B*CK_H),256>>>(p_sc, p_xv, p_ao, aoh);
    k_lora_down<<<CK_T,256>>>(p_ao, loA, p_uo);
    k_hgemm3<<<dim3(CK_D/128, CK_T/128),256,HG_SMEM>>>(aoh, wo_h, wo_l, p_d2, CK_T, CK_D, CK_D, p_uo, loB, CK_LS, data);

    // --- MoE path ---
    k_rmsnorm<<<CK_T,256>>>(p_d2, ffn_w, p_hn, hnh);
    k_gate<<<CK_T,256>>>(p_hn, gatew, p_route);
    k_expert_down<<<dim3(CK_T, CK_E),256>>>(p_hn, eA1, eA3, p_route, p_ua1, p_ua3);
    k_hgemm3<<<dim3(CK_FFN/128, CK_T/128),256,HG_SMEM>>>(hnh, w1_h, w1_l, p_h1, CK_T, CK_FFN, CK_D, nullptr, nullptr, 0.f, nullptr);
    k_hgemm3<<<dim3(CK_FFN/128, CK_T/128),256,HG_SMEM>>>(hnh, w3_h, w3_l, p_h3, CK_T, CK_FFN, CK_D, nullptr, nullptr, 0.f, nullptr);
    k_moe_expert<<<CK_T,256>>>(p_h1, p_h3, p_ua1, p_ua3, eB1h, eB3h, eA2h, p_route, gsh, p_v2);
    k_moe_up<<<CK_T,256>>>(p_d2, p_v2, eB2h, p_route, p_fpre);
    k_hgemm3<<<dim3(CK_D/128, CK_T/128),256,HG_SMEM>>>(gsh, w2_h, w2_l, out, CK_T, CK_D, CK_FFN, nullptr, nullptr, 0.f, p_fpre);
}

// round 9
// speedup vs baseline: 4.0276x; 1.4577x over previous
#include <cuda_runtime.h>
#include <cuda_fp16.h>
#include <math.h>
#include <stdint.h>

#define CK_B   4
#define CK_S   512
#define CK_D   2048
#define CK_H   16
#define CK_KV  4
#define CK_HD  128
#define CK_T   2048          // B*S
#define CK_FFN 5632
#define CK_E   8
#define CK_R   16
#define CK_LS  2.0f          // 32/16

// ---------------------------------------------------------------------------
// fp32 scratch
// ---------------------------------------------------------------------------
__device__ float g_h   [CK_T*CK_D];
__device__ float g_hn  [CK_T*CK_D];
__device__ float g_xq  [CK_T*CK_D];
__device__ float g_xk  [CK_T*CK_KV*CK_HD];
__device__ float g_xv  [CK_T*CK_KV*CK_HD];
__device__ float g_sc  [(size_t)CK_B*CK_H*CK_S*CK_S];
__device__ float g_ao  [CK_T*CK_D];
__device__ float g_d2  [CK_T*CK_D];
__device__ float g_uq  [CK_T*CK_R];
__device__ float g_uk  [CK_T*CK_R];
__device__ float g_uv  [CK_T*CK_R];
__device__ float g_uo  [CK_T*CK_R];
__device__ float g_route[CK_T*CK_E];
__device__ float g_ua1 [CK_T*CK_E*CK_R];
__device__ float g_ua3 [CK_T*CK_E*CK_R];
__device__ float g_h1  [(size_t)CK_T*CK_FFN];
__device__ float g_h3  [(size_t)CK_T*CK_FFN];
__device__ float g_v2  [CK_T*CK_E*CK_R];
__device__ float g_fpre[CK_T*CK_D];

// ---------------------------------------------------------------------------
// fp16 scratch
// ---------------------------------------------------------------------------
#define NWQ (CK_D*CK_D)
#define NWK (512*CK_D)
#define NW1 (CK_FFN*CK_D)
#define NEB (CK_E*CK_FFN*CK_R)
#define NB2 (CK_E*CK_D*CK_R)
__device__ __align__(16) __half g_wqh[NWQ];
__device__ __align__(16) __half g_wkh[NWK];
__device__ __align__(16) __half g_wvh[NWK];
__device__ __align__(16) __half g_woh[NWQ];
__device__ __align__(16) __half g_w1h[NW1];
__device__ __align__(16) __half g_w3h[NW1];
__device__ __align__(16) __half g_w2h[NW1];
__device__ __align__(16) __half g_xh [CK_T*CK_D];               // h  fp16
__device__ __align__(16) __half g_aoh[CK_T*CK_D];               // ao fp16
__device__ __align__(16) __half g_hnh[CK_T*CK_D];               // hn fp16
__device__ __align__(16) __half g_gsh[(size_t)CK_T*CK_FFN];     // ghs fp16
__device__ __align__(16) __half g_xqh[CK_T*CK_D];               // rope(q) fp16
__device__ __align__(16) __half g_xkh[CK_T*CK_KV*CK_HD];        // rope(k) fp16
__device__ __align__(16) __half g_vth[CK_T*CK_KV*CK_HD];        // V^T fp16
__device__ __align__(16) __half g_sch[(size_t)CK_B*CK_H*CK_S*CK_S]; // attn fp16
__device__ __align__(16) __half g_eB1h[NEB], g_eB3h[NEB], g_eA2h[NEB];
__device__ __align__(16) __half g_eB2h[NB2];

// ===========================================================================
// helpers
// ===========================================================================
__device__ __forceinline__ uint32_t smem_u32(const void* p) {
    uint32_t a;
    asm("{ .reg .u64 t; cvta.to.shared.u64 t, %1; cvt.u32.u64 %0, t; }" : "=r"(a) : "l"(p));
    return a;
}
#define CP_ASYNC16(dst_u32, src_ptr) \
    asm volatile("cp.async.cg.shared.global [%0], [%1], 16;" :: "r"(dst_u32), "l"(src_ptr))
#define CP_COMMIT() asm volatile("cp.async.commit_group;" ::: "memory")
#define CP_WAIT(n)  asm volatile("cp.async.wait_group %0;" :: "n"(n) : "memory")

__device__ __forceinline__ void mma16816(float* d, const uint32_t* a,
                                         uint32_t b0, uint32_t b1) {
    asm volatile(
        "mma.sync.aligned.m16n8k16.row.col.f32.f16.f16.f32 "
        "{%0,%1,%2,%3}, {%4,%5,%6,%7}, {%8,%9}, {%0,%1,%2,%3};"
        : "+f"(d[0]), "+f"(d[1]), "+f"(d[2]), "+f"(d[3])
        : "r"(a[0]), "r"(a[1]), "r"(a[2]), "r"(a[3]), "r"(b0), "r"(b1));
}

__device__ __forceinline__ void store4h(__half* p, float4 v) {
    *(__half2*)(p + 0) = __floats2half2_rn(v.x, v.y);
    *(__half2*)(p + 2) = __floats2half2_rn(v.z, v.w);
}

// fp32 -> fp16, 8 elems/thread
__global__ void k_half(const float* __restrict__ x, __half* __restrict__ h, int n) {
    int i = (blockIdx.x*256 + threadIdx.x)*8;
    if (i >= n) return;
    store4h(h + i,     *(const float4*)(x + i));
    store4h(h + i + 4, *(const float4*)(x + i + 4));
}

// ===========================================================================
// k_hgemm4: 1-pass fp16 tensor-core GEMM, cp.async double-buffered
//   C = A @ W^T [+ lscale*U@V^T] [+ res]
// ===========================================================================
#define HG_LD   40
#define HG_TILE (128*HG_LD)
#define HG_TILEB (HG_TILE*2)
#define HG_SMEM (4*HG_TILEB)     // 40960 bytes

__global__ void __launch_bounds__(256, 2) k_hgemm4(
    const __half* __restrict__ A, const __half* __restrict__ W,
    float* __restrict__ C, int M, int N, int K,
    const float* __restrict__ U, const float* __restrict__ V, float lscale,
    const float* __restrict__ res)
{
    extern __shared__ __align__(16) __half sm[];
    __half* pA = sm;                    // 2 bufs
    __half* pW = sm + 2*HG_TILE;        // 2 bufs
    const uint32_t sbA = smem_u32(sm);
    const uint32_t sbW = sbA + 2*HG_TILEB;

    const int tid  = threadIdx.x;
    const int wid  = tid >> 5, lane = tid & 31;
    const int g    = lane >> 2, tg = lane & 3;
    const int warpM = wid & 3;
    const int warpN = wid >> 2;
    const int bm = blockIdx.y * 128;
    const int bn = blockIdx.x * 128;

    float acc[2][8][4];
    #pragma unroll
    for (int mi = 0; mi < 2; mi++)
        #pragma unroll
        for (int ni = 0; ni < 8; ni++)
            #pragma unroll
            for (int q = 0; q < 4; q++) acc[mi][ni][q] = 0.f;

    const int NC = K / 32;
    const int total = NC + (U ? 1 : 0);

    auto load_async = [&](int c, int buf) {
        const int k0 = c * 32;
        const uint32_t bo = (uint32_t)buf * HG_TILEB;
        #pragma unroll
        for (int it = 0; it < 2; it++) {
            int id = it*256 + tid;
            int r = id >> 2, sg = (id & 3) * 8;
            uint32_t so = bo + (uint32_t)(r*HG_LD + sg)*2;
            CP_ASYNC16(sbA + so, A + (size_t)(bm + r)*K + k0 + sg);
            CP_ASYNC16(sbW + so, W + (size_t)(bn + r)*K + k0 + sg);
        }
        CP_COMMIT();
    };

    auto load_lora = [&](int buf) {
        __half* dA = pA + buf*HG_TILE;
        __half* dW = pW + buf*HG_TILE;
        #pragma unroll
        for (int l = 0; l < 4; l++) {
            int id = l*256 + tid;
            int r = id >> 3, c4 = (id & 7)*4;
            float4 va = make_float4(0.f,0.f,0.f,0.f);
            float4 vw = make_float4(0.f,0.f,0.f,0.f);
            if (c4 < 16) {
                va = *(const float4*)(U + (size_t)(bm + r)*16 + c4);
                va.x *= lscale; va.y *= lscale; va.z *= lscale; va.w *= lscale;
                vw = *(const float4*)(V + (size_t)(bn + r)*16 + c4);
            }
            store4h(dA + r*HG_LD + c4, va);
            store4h(dW + r*HG_LD + c4, vw);
        }
    };

    load_async(0, 0);

    for (int c = 0; c < total; c++) {
        const int cur = c & 1, nb = (c + 1) & 1;
        const bool have_next = (c + 1 < total);
        const bool next_async = (c + 1 < NC);
        if (have_next) {
            if (next_async) load_async(c + 1, nb);
            else            load_lora(nb);
        }
        if (c < NC) {
            if (have_next && next_async) { CP_WAIT(1); }
            else                         { CP_WAIT(0); }
        }
        __syncthreads();

        const __half* bA = pA + cur*HG_TILE;
        const __half* bW = pW + cur*HG_TILE;

        #pragma unroll
        for (int ks = 0; ks < 2; ks++) {
            const int col0 = ks*16 + tg*2;
            uint32_t a[2][4];
            #pragma unroll
            for (int mi = 0; mi < 2; mi++) {
                int r0 = warpM*32 + mi*16 + g;
                a[mi][0] = *(const uint32_t*)(bA + r0*HG_LD + col0);
                a[mi][1] = *(const uint32_t*)(bA + (r0+8)*HG_LD + col0);
                a[mi][2] = *(const uint32_t*)(bA + r0*HG_LD + col0 + 8);
                a[mi][3] = *(const uint32_t*)(bA + (r0+8)*HG_LD + col0 + 8);
            }
            #pragma unroll
            for (int ni = 0; ni < 8; ni++) {
                int rn = warpN*64 + ni*8 + g;
                uint32_t b0 = *(const uint32_t*)(bW + rn*HG_LD + col0);
                uint32_t b1 = *(const uint32_t*)(bW + rn*HG_LD + col0 + 8);
                #pragma unroll
                for (int mi = 0; mi < 2; mi++)
                    mma16816(acc[mi][ni], a[mi], b0, b1);
            }
        }
        __syncthreads();
    }

    #pragma unroll
    for (int mi = 0; mi < 2; mi++) {
        size_t r0 = (size_t)(bm + warpM*32 + mi*16 + g);
        #pragma unroll
        for (int ni = 0; ni < 8; ni++) {
            size_t c0 = (size_t)(bn + warpN*64 + ni*8 + tg*2);
            float2 o0 = make_float2(acc[mi][ni][0], acc[mi][ni][1]);
            float2 o1 = make_float2(acc[mi][ni][2], acc[mi][ni][3]);
            if (res) {
                float2 r0v = *(const float2*)(res + r0*N + c0);
                float2 r1v = *(const float2*)(res + (r0+8)*N + c0);
                o0.x += r0v.x; o0.y += r0v.y;
                o1.x += r1v.x; o1.y += r1v.y;
            }
            *(float2*)(C + r0*N + c0)     = o0;
            *(float2*)(C + (r0+8)*N + c0) = o1;
        }
    }
}

// ===========================================================================
// k_scores_h: scores = Q@K^T / sqrt(HD), fp16 tensor cores.
//   128x128 tile, whole K=128 staged once. Causal tile skip.
// ===========================================================================
#define SC_LD 136
#define SC_SMEM (2*128*SC_LD*2)   // 69632 bytes

__global__ void __launch_bounds__(256) k_scores_h(const __half* __restrict__ q,
                                                  const __half* __restrict__ k,
                                                  float* __restrict__ sc) {
    const int t0 = blockIdx.x*128, s0 = blockIdx.y*128;
    if (t0 > s0) return;
    const int bh = blockIdx.z, b = bh >> 4, h = bh & 15, kv = h >> 2;
    extern __shared__ __align__(16) __half sm[];
    __half* Qs = sm;
    __half* Ks = sm + 128*SC_LD;

    const int tid = threadIdx.x;
    const int wid = tid >> 5, lane = tid & 31;
    const int g = lane >> 2, tg = lane & 3;
    const int warpM = wid & 3, warpN = wid >> 2;

    #pragma unroll
    for (int it = 0; it < 8; it++) {
        int id = it*256 + tid;
        int r = id >> 4, c8 = (id & 15)*8;
        *(uint4*)(Qs + r*SC_LD + c8) =
            *(const uint4*)(q + ((size_t)(b*CK_S + s0 + r)*CK_D + h*CK_HD + c8));
        *(uint4*)(Ks + r*SC_LD + c8) =
            *(const uint4*)(k + ((size_t)(b*CK_S + t0 + r)*(CK_KV*CK_HD) + kv*CK_HD + c8));
    }
    __syncthreads();

    float acc[2][8][4];
    #pragma unroll
    for (int mi = 0; mi < 2; mi++)
        #pragma unroll
        for (int ni = 0; ni < 8; ni++)
            #pragma unroll
            for (int qq = 0; qq < 4; qq++) acc[mi][ni][qq] = 0.f;

    #pragma unroll
    for (int ks = 0; ks < 8; ks++) {
        const int col0 = ks*16 + tg*2;
        uint32_t a[2][4];
        #pragma unroll
        for (int mi = 0; mi < 2; mi++) {
            int r0 = warpM*32 + mi*16 + g;
            a[mi][0] = *(const uint32_t*)(Qs + r0*SC_LD + col0);
            a[mi][1] = *(const uint32_t*)(Qs + (r0+8)*SC_LD + col0);
            a[mi][2] = *(const uint32_t*)(Qs + r0*SC_LD + col0 + 8);
            a[mi][3] = *(const uint32_t*)(Qs + (r0+8)*SC_LD + col0 + 8);
        }
        #pragma unroll
        for (int ni = 0; ni < 8; ni++) {
            int rn = warpN*64 + ni*8 + g;
            uint32_t b0 = *(const uint32_t*)(Ks + rn*SC_LD + col0);
            uint32_t b1 = *(const uint32_t*)(Ks + rn*SC_LD + col0 + 8);
            #pragma unroll
            for (int mi = 0; mi < 2; mi++)
                mma16816(acc[mi][ni], a[mi], b0, b1);
        }
    }

    const float scl = 0.08838834764831845f;   // 1/sqrt(128)
    float* out = sc + (size_t)bh*CK_S*CK_S;
    #pragma unroll
    for (int mi = 0; mi < 2; mi++) {
        size_t r0 = (size_t)(s0 + warpM*32 + mi*16 + g);
        #pragma unroll
        for (int ni = 0; ni < 8; ni++) {
            size_t c0 = (size_t)(t0 + warpN*64 + ni*8 + tg*2);
            *(float2*)(out + r0*CK_S + c0) =
                make_float2(acc[mi][ni][0]*scl, acc[mi][ni][1]*scl);
            *(float2*)(out + (r0+8)*CK_S + c0) =
                make_float2(acc[mi][ni][2]*scl, acc[mi][ni][3]*scl);
        }
    }
}

// ===========================================================================
// k_avh: out = attn(fp16) @ V^T(fp16), causal K-bound, tensor cores.
//   M=128 (s), N=128 (hd), K chunks of 32 up to s0+128.
// ===========================================================================
__global__ void __launch_bounds__(256, 2) k_avh(const __half* __restrict__ attn,
                                                const __half* __restrict__ vt,
                                                float* __restrict__ out,
                                                __half* __restrict__ outh) {
    extern __shared__ __align__(16) __half sm[];
    __half* pA = sm;
    __half* pW = sm + 2*HG_TILE;
    const uint32_t sbA = smem_u32(sm);
    const uint32_t sbW = sbA + 2*HG_TILEB;

    const int s0 = blockIdx.y * 128;
    const int bh = blockIdx.z, b = bh >> 4, h = bh & 15, kv = h >> 2;
    const __half* Ab = attn + (size_t)bh*CK_S*CK_S;
    const __half* Wb = vt + ((size_t)(b*CK_KV + kv)*CK_HD)*CK_S;

    const int tid = threadIdx.x;
    const int wid = tid >> 5, lane = tid & 31;
    const int g = lane >> 2, tg = lane & 3;
    const int warpM = wid & 3, warpN = wid >> 2;

    float acc[2][8][4];
    #pragma unroll
    for (int mi = 0; mi < 2; mi++)
        #pragma unroll
        for (int ni = 0; ni < 8; ni++)
            #pragma unroll
            for (int q = 0; q < 4; q++) acc[mi][ni][q] = 0.f;

    const int NC = (s0 + 128) / 32;

    auto load_async = [&](int c, int buf) {
        const int k0 = c * 32;
        const uint32_t bo = (uint32_t)buf * HG_TILEB;
        #pragma unroll
        for (int it = 0; it < 2; it++) {
            int id = it*256 + tid;
            int r = id >> 2, sg = (id & 3) * 8;
            uint32_t so = bo + (uint32_t)(r*HG_LD + sg)*2;
            CP_ASYNC16(sbA + so, Ab + (size_t)(s0 + r)*CK_S + k0 + sg);
            CP_ASYNC16(sbW + so, Wb + (size_t)r*CK_S + k0 + sg);
        }
        CP_COMMIT();
    };

    load_async(0, 0);
    for (int c = 0; c < NC; c++) {
        const int cur = c & 1;
        if (c + 1 < NC) { load_async(c + 1, (c+1)&1); CP_WAIT(1); }
        else            { CP_WAIT(0); }
        __syncthreads();

        const __half* bA = pA + cur*HG_TILE;
        const __half* bW = pW + cur*HG_TILE;
        #pragma unroll
        for (int ks = 0; ks < 2; ks++) {
            const int col0 = ks*16 + tg*2;
            uint32_t a[2][4];
            #pragma unroll
            for (int mi = 0; mi < 2; mi++) {
                int r0 = warpM*32 + mi*16 + g;
                a[mi][0] = *(const uint32_t*)(bA + r0*HG_LD + col0);
                a[mi][1] = *(const uint32_t*)(bA + (r0+8)*HG_LD + col0);
                a[mi][2] = *(const uint32_t*)(bA + r0*HG_LD + col0 + 8);
                a[mi][3] = *(const uint32_t*)(bA + (r0+8)*HG_LD + col0 + 8);
            }
            #pragma unroll
            for (int ni = 0; ni < 8; ni++) {
                int rn = warpN*64 + ni*8 + g;
                uint32_t b0 = *(const uint32_t*)(bW + rn*HG_LD + col0);
                uint32_t b1 = *(const uint32_t*)(bW + rn*HG_LD + col0 + 8);
                #pragma unroll
                for (int mi = 0; mi < 2; mi++)
                    mma16816(acc[mi][ni], a[mi], b0, b1);
            }
        }
        __syncthreads();
    }

    #pragma unroll
    for (int mi = 0; mi < 2; mi++) {
        int s = s0 + warpM*32 + mi*16 + g;
        #pragma unroll
        for (int ni = 0; ni < 8; ni++) {
            int c0 = warpN*64 + ni*8 + tg*2;
            size_t off0 = ((size_t)(b*CK_S + s)*CK_H + h)*CK_HD + c0;
            size_t off1 = ((size_t)(b*CK_S + s + 8)*CK_H + h)*CK_HD + c0;
            *(float2*)(out + off0) = make_float2(acc[mi][ni][0], acc[mi][ni][1]);
            *(float2*)(out + off1) = make_float2(acc[mi][ni][2], acc[mi][ni][3]);
            *(__half2*)(outh + off0) = __floats2half2_rn(acc[mi][ni][0], acc[mi][ni][1]);
            *(__half2*)(outh + off1) = __floats2half2_rn(acc[mi][ni][2], acc[mi][ni][3]);
        }
    }
}

// ---------------------------------------------------------------------------
// k_vt: V fp32 [t][kv*HD] -> V^T fp16 [b][kv][hd][s]
// ---------------------------------------------------------------------------
__global__ void k_vt(const float* __restrict__ xv, __half* __restrict__ vt) {
    int bkv = blockIdx.z, b = bkv >> 2, kv = bkv & 3;
    int s0 = blockIdx.x*32, h0 = blockIdx.y*32;
    __shared__ __half t[32][33];
    int x = threadIdx.x & 31, y = threadIdx.x >> 5;
    for (int i = y; i < 32; i += 8)
        t[i][x] = __float2half_rn(
            xv[(size_t)(b*CK_S + s0 + i)*(CK_KV*CK_HD) + kv*CK_HD + h0 + x]);
    __syncthreads();
    for (int i = y; i < 32; i += 8)
        vt[((size_t)bkv*CK_HD + h0 + i)*CK_S + s0 + x] = t[x][i];
}

// ---------------------------------------------------------------------------
// RMSNorm (fp32 out + fp16 out)
// ---------------------------------------------------------------------------
__global__ void k_rmsnorm(const float* __restrict__ x, const float* __restrict__ w,
                          float* __restrict__ o, __half* __restrict__ oh) {
    int t = blockIdx.x;
    const float* xr = x + (size_t)t*CK_D;
    float ss = 0.f;
    for (int i = threadIdx.x; i < CK_D; i += 256) { float v = xr[i]; ss += v*v; }
    __shared__ float red[256];
    red[threadIdx.x] = ss; __syncthreads();
    for (int s = 128; s > 0; s >>= 1) {
        if (threadIdx.x < s) red[threadIdx.x] += red[threadIdx.x+s];
        __syncthreads();
    }
    float sc = rsqrtf(red[0]/(float)CK_D + 1e-5f);
    float* orow = o + (size_t)t*CK_D;
    __half* hrow = oh + (size_t)t*CK_D;
    for (int i = threadIdx.x; i < CK_D; i += 256) {
        float r = xr[i]*sc*w[i];
        orow[i] = r;
        hrow[i] = __float2half_rn(r);
    }
}

// ---------------------------------------------------------------------------
// Fused q/k/v LoRA downs (single read of X)
// ---------------------------------------------------------------------------
__global__ void k_lora_down3(const float* __restrict__ X,
                             const float* __restrict__ A1, const float* __restrict__ A2,
                             const float* __restrict__ A3,
                             float* __restrict__ U1, float* __restrict__ U2,
                             float* __restrict__ U3) {
    int t = blockIdx.x;
    __shared__ float sx[CK_D];
    for (int i = threadIdx.x; i < CK_D; i += 256) sx[i] = X[(size_t)t*CK_D + i];
    __syncthreads();
    int w = threadIdx.x >> 5, lane = threadIdx.x & 31;
    for (int rr = w; rr < 48; rr += 8) {
        int m = rr >> 4, r = rr & 15;
        const float* ar = (m == 0 ? A1 : m == 1 ? A2 : A3) + (size_t)r*CK_D;
        float p = 0.f;
        for (int d = lane; d < CK_D; d += 32) p += sx[d]*ar[d];
        for (int o = 16; o; o >>= 1) p += __shfl_down_sync(0xffffffffu, p, o);
        if (lane == 0) (m == 0 ? U1 : m == 1 ? U2 : U3)[t*CK_R + r] = p;
    }
}

__global__ void k_lora_down(const float* __restrict__ X, const float* __restrict__ A,
                            float* __restrict__ U) {
    int t = blockIdx.x;
    __shared__ float sx[CK_D];
    for (int i = threadIdx.x; i < CK_D; i += 256) sx[i] = X[(size_t)t*CK_D + i];
    __syncthreads();
    int w = threadIdx.x >> 5, lane = threadIdx.x & 31;
    for (int r = w; r < CK_R; r += 8) {
        const float* ar = A + (size_t)r*CK_D;
        float p = 0.f;
        for (int d = lane; d < CK_D; d += 32) p += sx[d]*ar[d];
        for (int o = 16; o; o >>= 1) p += __shfl_down_sync(0xffffffffu, p, o);
        if (lane == 0) U[t*CK_R + r] = p;
    }
}

// ---------------------------------------------------------------------------
// RoPE: read fp32, write fp16
// ---------------------------------------------------------------------------
__global__ void k_rope(const float* __restrict__ x, const float* __restrict__ cs,
                       const float* __restrict__ sn, int nh, int total,
                       __half* __restrict__ oh) {
    int i = blockIdx.x*256 + threadIdx.x;
    if (i >= total) return;
    int d2 = i & 63;
    int h  = (i >> 6) % nh;
    int t  = i / (64*nh);
    int s  = t & (CK_S - 1);
    float c  = cs[s*64 + d2];
    float si = sn[s*64 + d2];
    size_t off = ((size_t)t*nh + h)*CK_HD + 2*d2;
    float x1 = x[off], x2 = x[off + 1];
    *(__half2*)(oh + off) = __floats2half2_rn(x1*c - x2*si, x1*si + x2*c);
}

// ---------------------------------------------------------------------------
// Causal softmax: fp32 scores in, fp16 attn out (zeros beyond diagonal)
// ---------------------------------------------------------------------------
__global__ void k_softmax(const float* __restrict__ sc, __half* __restrict__ sch) {
    int row = blockIdx.x;            // bh*512 + s
    int s = row & (CK_S - 1);
    const float* p = sc + (size_t)row*CK_S;
    __half* ph = sch + (size_t)row*CK_S;
    int L = s + 1;
    int tid = threadIdx.x;
    float v0 = (tid       < L) ? p[tid]       : -1e30f;
    float v1 = (tid + 256 < L) ? p[tid + 256] : -1e30f;
    __shared__ float red[256];
    red[tid] = fmaxf(v0, v1); __syncthreads();
    for (int st = 128; st; st >>= 1) {
        if (tid < st) red[tid] = fmaxf(red[tid], red[tid+st]);
        __syncthreads();
    }
    float m = red[0]; __syncthreads();
    float e0 = (tid       < L) ? expf(v0 - m) : 0.f;
    float e1 = (tid + 256 < L) ? expf(v1 - m) : 0.f;
    red[tid] = e0 + e1; __syncthreads();
    for (int st = 128; st; st >>= 1) {
        if (tid < st) red[tid] += red[tid+st];
        __syncthreads();
    }
    float inv = 1.f / red[0];
    ph[tid]       = __float2half_rn(e0 * inv);
    ph[tid + 256] = __float2half_rn(e1 * inv);
}

// ---------------------------------------------------------------------------
// Gate
// ---------------------------------------------------------------------------
__global__ void k_gate(const float* __restrict__ hn, const float* __restrict__ gw,
                       float* __restrict__ route) {
    int t = blockIdx.x;
    __shared__ float sl[8];
    int w = threadIdx.x >> 5, lane = threadIdx.x & 31;
    const float* xr = hn + (size_t)t*CK_D;
    const float* gr = gw + (size_t)w*CK_D;
    float p = 0.f;
    for (int d = lane; d < CK_D; d += 32) p += xr[d]*gr[d];
    for (int o = 16; o; o >>= 1) p += __shfl_down_sync(0xffffffffu, p, o);
    if (lane == 0) sl[w] = p;
    __syncthreads();
    if (threadIdx.x == 0) {
        int i0 = 0;
        for (int e = 1; e < 8; e++) if (sl[e] > sl[i0]) i0 = e;
        int i1 = -1;
        for (int e = 0; e < 8; e++) { if (e == i0) continue; if (i1 < 0 || sl[e] > sl[i1]) i1 = e; }
        float m = sl[i0];
        float v0 = expf(sl[i0]-m), v1 = expf(sl[i1]-m);
        float inv = 1.f/(v0+v1);
        float* rr = route + (size_t)t*CK_E;
        #pragma unroll
        for (int e = 0; e < 8; e++) rr[e] = 0.f;
        rr[i0] = v0*inv; rr[i1] = v1*inv;
    }
}

// ---------------------------------------------------------------------------
// Expert LoRA downs
// ---------------------------------------------------------------------------
__global__ void k_expert_down(const float* __restrict__ X, const float* __restrict__ A1,
                              const float* __restrict__ A3, const float* __restrict__ route,
                              float* __restrict__ U1, float* __restrict__ U3) {
    int t = blockIdx.x, e = blockIdx.y;
    if (route[t*CK_E + e] == 0.f) return;
    __shared__ float sx[CK_D];
    for (int i = threadIdx.x; i < CK_D; i += 256) sx[i] = X[(size_t)t*CK_D + i];
    __syncthreads();
    int w = threadIdx.x >> 5, lane = threadIdx.x & 31;
    const float* a1 = A1 + (size_t)e*CK_R*CK_D;
    const float* a3 = A3 + (size_t)e*CK_R*CK_D;
    for (int r = w; r < CK_R; r += 8) {
        float p1 = 0.f, p3 = 0.f;
        for (int d = lane; d < CK_D; d += 32) {
            float xv = sx[d];
            p1 += xv*a1[(size_t)r*CK_D + d];
            p3 += xv*a3[(size_t)r*CK_D + d];
        }
        for (int o = 16; o; o >>= 1) {
            p1 += __shfl_down_sync(0xffffffffu, p1, o);
            p3 += __shfl_down_sync(0xffffffffu, p3, o);
        }
        if (lane == 0) {
            U1[((size_t)t*CK_E + e)*CK_R + r] = p1;
            U3[((size_t)t*CK_E + e)*CK_R + r] = p3;
        }
    }
}

// ---------------------------------------------------------------------------
// Fused per-token MoE combine
// ---------------------------------------------------------------------------
__device__ __forceinline__ void h8f(const __half* p, float* f) {
    uint4 q = *(const uint4*)p;
    const __half2* hp = (const __half2*)&q;
    #pragma unroll
    for (int j = 0; j < 4; j++) {
        float2 t = __half22float2(hp[j]);
        f[2*j] = t.x; f[2*j+1] = t.y;
    }
}

__global__ void __launch_bounds__(256) k_moe_expert(
    const float* __restrict__ h1, const float* __restrict__ h3,
    const float* __restrict__ ua1, const float* __restrict__ ua3,
    const __half* __restrict__ eB1, const __half* __restrict__ eB3,
    const __half* __restrict__ eA2, const float* __restrict__ route,
    __half* __restrict__ ghs, float* __restrict__ v2)
{
    const int t = blockIdx.x;
    const int tid = threadIdx.x;
    const int wid = tid >> 5, lane = tid & 31;
    const int NI = CK_FFN/256;   // 22
    float ghacc[CK_FFN/256];
    #pragma unroll
    for (int i = 0; i < NI; i++) ghacc[i] = 0.f;
    __shared__ float su1[16], su3[16];
    __shared__ float part[8][16];
    const float* h1r = h1 + (size_t)t*CK_FFN;
    const float* h3r = h3 + (size_t)t*CK_FFN;

    #pragma unroll 1
    for (int e = 0; e < CK_E; e++) {
        float wgt = route[t*CK_E + e];
        if (wgt == 0.f) {
            if (tid < 16) v2[(size_t)t*(CK_E*CK_R) + e*16 + tid] = 0.f;
            continue;
        }
        if (tid < 16) {
            su1[tid] = ua1[((size_t)t*CK_E + e)*16 + tid];
            su3[tid] = ua3[((size_t)t*CK_E + e)*16 + tid];
        }
        __syncthreads();
        float u1[16], u3[16];
        #pragma unroll
        for (int r = 0; r < 16; r++) { u1[r] = su1[r]; u3[r] = su3[r]; }
        float accr[16];
        #pragma unroll
        for (int r = 0; r < 16; r++) accr[r] = 0.f;
        const __half* B1 = eB1 + (size_t)e*CK_FFN*16;
        const __half* B3 = eB3 + (size_t)e*CK_FFN*16;
        const __half* A2 = eA2 + (size_t)e*16*CK_FFN;
        #pragma unroll
        for (int ii = 0; ii < NI; ii++) {
            int f = ii*256 + tid;
            float b1v[16], b3v[16];
            h8f(B1 + (size_t)f*16,     b1v);
            h8f(B1 + (size_t)f*16 + 8, b1v + 8);
            h8f(B3 + (size_t)f*16,     b3v);
            h8f(B3 + (size_t)f*16 + 8, b3v + 8);
            float b1 = 0.f, b3 = 0.f;
            #pragma unroll
            for (int r = 0; r < 16; r++) { b1 += u1[r]*b1v[r]; b3 += u3[r]*b3v[r]; }
            float g1 = h1r[f] + CK_LS*b1;
            float g3 = h3r[f] + CK_LS*b3;
            float gh = (g1/(1.f + expf(-g1)))*g3;
            ghacc[ii] += wgt*gh;
            #pragma unroll
            for (int r = 0; r < 16; r++)
                accr[r] += gh * __half2float(A2[(size_t)r*CK_FFN + f]);
        }
        #pragma unroll
        for (int r = 0; r < 16; r++) {
            float v = accr[r];
            #pragma unroll
            for (int o = 16; o; o >>= 1) v += __shfl_down_sync(0xffffffffu, v, o);
            if (lane == 0) part[wid][r] = v;
        }
        __syncthreads();
        if (tid < 16) {
            float s2 = 0.f;
            #pragma unroll
            for (int ww = 0; ww < 8; ww++) s2 += part[ww][tid];
            v2[(size_t)t*(CK_E*CK_R) + e*16 + tid] = wgt*CK_LS*s2;
        }
        __syncthreads();
    }
    __half* go = ghs + (size_t)t*CK_FFN;
    #pragma unroll
    for (int ii = 0; ii < NI; ii++) go[ii*256 + tid] = __float2half_rn(ghacc[ii]);
}

// ---------------------------------------------------------------------------
// fpre = data2 + v2 @ eB2^T
// ---------------------------------------------------------------------------
__global__ void k_moe_up(const float* __restrict__ d2, const float* __restrict__ v2,
                         const __half* __restrict__ eB2, const float* __restrict__ route,
                         float* __restrict__ out) {
    int t = blockIdx.x, tid = threadIdx.x;
    __shared__ float sv[128];
    __shared__ int act[8];
    if (tid < 128) sv[tid] = v2[(size_t)t*128 + tid];
    if (tid < 8)   act[tid] = (route[t*CK_E + tid] != 0.f) ? 1 : 0;
    __syncthreads();
    for (int d = tid; d < CK_D; d += 256) {
        float s = d2[(size_t)t*CK_D + d];
        #pragma unroll 1
        for (int e = 0; e < 8; e++) {
            if (!act[e]) continue;
            float bv[16];
            const __half* bp = eB2 + ((size_t)e*CK_D + d)*16;
            h8f(bp, bv); h8f(bp + 8, bv + 8);
            #pragma unroll
            for (int r = 0; r < 16; r++) s += sv[e*16+r]*bv[r];
        }
        out[(size_t)t*CK_D + d] = s;
    }
}

// ---------------------------------------------------------------------------
// Launch
// ---------------------------------------------------------------------------
extern "C" void kernel_launch(void* const* d_in, const int* in_sizes, int n_in,
                              void* d_out, int out_size) {
    (void)in_sizes; (void)n_in; (void)out_size;
    const float* data  = (const float*)d_in[0];
    const float* rc    = (const float*)d_in[2];
    const float* rs    = (const float*)d_in[3];
    const float* att_w = (const float*)d_in[4];
    const float* ffn_w = (const float*)d_in[5];
    const float* wq    = (const float*)d_in[6];
    const float* wk    = (const float*)d_in[7];
    const float* wv    = (const float*)d_in[8];
    const float* wo    = (const float*)d_in[9];
    const float* lqA   = (const float*)d_in[10];
    const float* lqB   = (const float*)d_in[11];
    const float* lkA   = (const float*)d_in[12];
    const float* lkB   = (const float*)d_in[13];
    const float* lvA   = (const float*)d_in[14];
    const float* lvB   = (const float*)d_in[15];
    const float* loA   = (const float*)d_in[16];
    const float* loB   = (const float*)d_in[17];
    const float* w1    = (const float*)d_in[18];
    const float* w2    = (const float*)d_in[19];
    const float* w3    = (const float*)d_in[20];
    const float* gatew = (const float*)d_in[21];
    const float* eA1   = (const float*)d_in[22];
    const float* eB1   = (const float*)d_in[23];
    const float* eA2   = (const float*)d_in[24];
    const float* eB2   = (const float*)d_in[25];
    const float* eA3   = (const float*)d_in[26];
    const float* eB3   = (const float*)d_in[27];
    float* out = (float*)d_out;

    float *p_h,*p_hn,*p_xq,*p_xk,*p_xv,*p_sc,*p_ao,*p_d2,*p_uq,*p_uk,*p_uv,*p_uo;
    float *p_route,*p_ua1,*p_ua3,*p_h1,*p_h3,*p_v2,*p_fpre;
    cudaGetSymbolAddress((void**)&p_h,    g_h);
    cudaGetSymbolAddress((void**)&p_hn,   g_hn);
    cudaGetSymbolAddress((void**)&p_xq,   g_xq);
    cudaGetSymbolAddress((void**)&p_xk,   g_xk);
    cudaGetSymbolAddress((void**)&p_xv,   g_xv);
    cudaGetSymbolAddress((void**)&p_sc,   g_sc);
    cudaGetSymbolAddress((void**)&p_ao,   g_ao);
    cudaGetSymbolAddress((void**)&p_d2,   g_d2);
    cudaGetSymbolAddress((void**)&p_uq,   g_uq);
    cudaGetSymbolAddress((void**)&p_uk,   g_uk);
    cudaGetSymbolAddress((void**)&p_uv,   g_uv);
    cudaGetSymbolAddress((void**)&p_uo,   g_uo);
    cudaGetSymbolAddress((void**)&p_route,g_route);
    cudaGetSymbolAddress((void**)&p_ua1,  g_ua1);
    cudaGetSymbolAddress((void**)&p_ua3,  g_ua3);
    cudaGetSymbolAddress((void**)&p_h1,   g_h1);
    cudaGetSymbolAddress((void**)&p_h3,   g_h3);
    cudaGetSymbolAddress((void**)&p_v2,   g_v2);
    cudaGetSymbolAddress((void**)&p_fpre, g_fpre);

    __half *wqh,*wkh,*wvh,*woh,*w1h,*w3h,*w2h;
    __half *xh,*aoh,*hnh,*gsh,*xqh,*xkh,*vth,*sch,*eB1h,*eB3h,*eA2h,*eB2h;
    cudaGetSymbolAddress((void**)&wqh, g_wqh);
    cudaGetSymbolAddress((void**)&wkh, g_wkh);
    cudaGetSymbolAddress((void**)&wvh, g_wvh);
    cudaGetSymbolAddress((void**)&woh, g_woh);
    cudaGetSymbolAddress((void**)&w1h, g_w1h);
    cudaGetSymbolAddress((void**)&w3h, g_w3h);
    cudaGetSymbolAddress((void**)&w2h, g_w2h);
    cudaGetSymbolAddress((void**)&xh,  g_xh);
    cudaGetSymbolAddress((void**)&aoh, g_aoh);
    cudaGetSymbolAddress((void**)&hnh, g_hnh);
    cudaGetSymbolAddress((void**)&gsh, g_gsh);
    cudaGetSymbolAddress((void**)&xqh, g_xqh);
    cudaGetSymbolAddress((void**)&xkh, g_xkh);
    cudaGetSymbolAddress((void**)&vth, g_vth);
    cudaGetSymbolAddress((void**)&sch, g_sch);
    cudaGetSymbolAddress((void**)&eB1h, g_eB1h);
    cudaGetSymbolAddress((void**)&eB3h, g_eB3h);
    cudaGetSymbolAddress((void**)&eA2h, g_eA2h);
    cudaGetSymbolAddress((void**)&eB2h, g_eB2h);

    cudaFuncSetAttribute(k_hgemm4,   cudaFuncAttributeMaxDynamicSharedMemorySize, HG_SMEM);
    cudaFuncSetAttribute(k_scores_h, cudaFuncAttributeMaxDynamicSharedMemorySize, SC_SMEM);
    cudaFuncSetAttribute(k_avh,      cudaFuncAttributeMaxDynamicSharedMemorySize, HG_SMEM);

    // --- weight/expert-mat conversions ---
    k_half<<<NWQ/2048,256>>>(wq, wqh, NWQ);
    k_half<<<NWK/2048,256>>>(wk, wkh, NWK);
    k_half<<<NWK/2048,256>>>(wv, wvh, NWK);
    k_half<<<NWQ/2048,256>>>(wo, woh, NWQ);
    k_half<<<NW1/2048,256>>>(w1, w1h, NW1);
    k_half<<<NW1/2048,256>>>(w3, w3h, NW1);
    k_half<<<NW1/2048,256>>>(w2, w2h, NW1);
    k_half<<<NEB/2048,256>>>(eB1, eB1h, NEB);
    k_half<<<NEB/2048,256>>>(eB3, eB3h, NEB);
    k_half<<<NEB/2048,256>>>(eA2, eA2h, NEB);
    k_half<<<NB2/2048,256>>>(eB2, eB2h, NB2);

    // --- attention path ---
    k_rmsnorm<<<CK_T,256>>>(data, att_w, p_h, xh);
    k_lora_down3<<<CK_T,256>>>(p_h, lqA, lkA, lvA, p_uq, p_uk, p_uv);
    k_hgemm4<<<dim3(CK_D/128, CK_T/128),256,HG_SMEM>>>(xh, wqh, p_xq, CK_T, CK_D, CK_D, p_uq, lqB, CK_LS, nullptr);
    k_hgemm4<<<dim3(512/128,  CK_T/128),256,HG_SMEM>>>(xh, wkh, p_xk, CK_T, 512,  CK_D, p_uk, lkB, CK_LS, nullptr);
    k_hgemm4<<<dim3(512/128,  CK_T/128),256,HG_SMEM>>>(xh, wvh, p_xv, CK_T, 512,  CK_D, p_uv, lvB, CK_LS, nullptr);
    k_rope<<<(CK_T*CK_H*64 + 255)/256, 256>>>(p_xq, rc, rs, CK_H,  CK_T*CK_H*64,  xqh);
    k_rope<<<(CK_T*CK_KV*64 + 255)/256,256>>>(p_xk, rc, rs, CK_KV, CK_T*CK_KV*64, xkh);
    k_vt<<<dim3(CK_S/32, CK_HD/32, CK_B*CK_KV),256>>>(p_xv, vth);
    k_scores_h<<<dim3(CK_S/128, CK_S/128, CK_B*CK_H),256,SC_SMEM>>>(xqh, xkh, p_sc);
    k_softmax<<<CK_B*CK_H*CK_S,256>>>(p_sc, sch);
    k_avh<<<dim3(1, CK_S/128, CK_B*CK_H),256,HG_SMEM>>>(sch, vth, p_ao, aoh);
    k_lora_down<<<CK_T,256>>>(p_ao, loA, p_uo);
    k_hgemm4<<<dim3(CK_D/128, CK_T/128),256,HG_SMEM>>>(aoh, woh, p_d2, CK_T, CK_D, CK_D, p_uo, loB, CK_LS, data);

    // --- MoE path ---
    k_rmsnorm<<<CK_T,256>>>(p_d2, ffn_w, p_hn, hnh);
    k_gate<<<CK_T,256>>>(p_hn, gatew, p_route);
    k_expert_down<<<dim3(CK_T, CK_E),256>>>(p_hn, eA1, eA3, p_route, p_ua1, p_ua3);
    k_hgemm4<<<dim3(CK_FFN/128, CK_T/128),256,HG_SMEM>>>(hnh, w1h, p_h1, CK_T, CK_FFN, CK_D, nullptr, nullptr, 0.f, nullptr);
    k_hgemm4<<<dim3(CK_FFN/128, CK_T/128),256,HG_SMEM>>>(hnh, w3h, p_h3, CK_T, CK_FFN, CK_D, nullptr, nullptr, 0.f, nullptr);
    k_moe_expert<<<CK_T,256>>>(p_h1, p_h3, p_ua1, p_ua3, eB1h, eB3h, eA2h, p_route, gsh, p_v2);
    k_moe_up<<<CK_T,256>>>(p_d2, p_v2, eB2h, p_route, p_fpre);
    k_hgemm4<<<dim3(CK_D/128, CK_T/128),256,HG_SMEM>>>(gsh, w2h, out, CK_T, CK_D, CK_FFN, nullptr, nullptr, 0.f, p_fpre);
}